// round 5
// baseline (speedup 1.0000x reference)
#include <cuda_runtime.h>
#include <math.h>

#define NN   50000
#define NF   256
#define NHID 128
#define KHOP 4
#define NC   512      // KHOP * NHID, concat width
#define NE   800000
#define NO   64

// Scratch: h (post-linear per-hop features, hop-blocked columns) and agg
// (post-SpMM accumulator). 102.4 MB each, __device__ globals per harness rules.
__device__ float g_h[(size_t)NN * NC];
__device__ float g_agg[(size_t)NN * NC];

// ---------------------------------------------------------------------------
// Zero the aggregation buffer (must happen every call: atomics accumulate).
// ---------------------------------------------------------------------------
__global__ __launch_bounds__(256) void zero_agg() {
    const size_t n4 = (size_t)NN * NC / 4;
    float4* p = reinterpret_cast<float4*>(g_agg);
    const float4 z = make_float4(0.f, 0.f, 0.f, 0.f);
    for (size_t i = (size_t)blockIdx.x * blockDim.x + threadIdx.x;
         i < n4; i += (size_t)gridDim.x * blockDim.x)
        p[i] = z;
}

// ---------------------------------------------------------------------------
// GEMM1: g_h[n, hop*128 + j] = sum_f x[n,f] * W[hop,f,j] + b[hop,j]
// Tile 128x128, BK=8, 256 threads, 8x8 micro-tile per thread.
// blockIdx.x = hop (N-block of 128 == one hop), blockIdx.y = M-block.
// ---------------------------------------------------------------------------
__global__ __launch_bounds__(256) void gemm1(const float* __restrict__ x,
                                             const float* __restrict__ W,
                                             const float* __restrict__ bias) {
    const int hop = blockIdx.x;
    const int m0  = blockIdx.y * 128;

    __shared__ float As[8][128];   // transposed: As[k][m]
    __shared__ float Bs[8][128];   // Bs[k][n]

    const int t  = threadIdx.x;
    const int tx = t & 15;         // n-tile index (8 cols each)
    const int ty = t >> 4;         // m-tile index (8 rows each)

    const float* Wp = W + (size_t)hop * NF * NHID;

    const int a_row = t >> 1;           // 0..127
    const int a_col = (t & 1) * 4;      // 0 or 4
    const int b_row = t >> 5;           // 0..7
    const int b_col = (t & 31) * 4;     // 0..124
    const int gr    = m0 + a_row;

    float acc[8][8];
#pragma unroll
    for (int i = 0; i < 8; i++)
#pragma unroll
        for (int j = 0; j < 8; j++) acc[i][j] = 0.f;

    for (int k0 = 0; k0 < NF; k0 += 8) {
        float4 av = make_float4(0.f, 0.f, 0.f, 0.f);
        if (gr < NN)
            av = *reinterpret_cast<const float4*>(x + (size_t)gr * NF + k0 + a_col);
        const float4 bv =
            *reinterpret_cast<const float4*>(Wp + (size_t)(k0 + b_row) * NHID + b_col);

        __syncthreads();
        As[a_col + 0][a_row] = av.x;
        As[a_col + 1][a_row] = av.y;
        As[a_col + 2][a_row] = av.z;
        As[a_col + 3][a_row] = av.w;
        *reinterpret_cast<float4*>(&Bs[b_row][b_col]) = bv;
        __syncthreads();

#pragma unroll
        for (int kk = 0; kk < 8; kk++) {
            float a[8], bb[8];
#pragma unroll
            for (int i = 0; i < 8; i++) a[i] = As[kk][ty * 8 + i];
#pragma unroll
            for (int j = 0; j < 8; j++) bb[j] = Bs[kk][tx * 8 + j];
#pragma unroll
            for (int i = 0; i < 8; i++)
#pragma unroll
                for (int j = 0; j < 8; j++)
                    acc[i][j] = fmaf(a[i], bb[j], acc[i][j]);
        }
    }

    // Epilogue: add bias, store into hop-blocked column range of g_h.
#pragma unroll
    for (int i = 0; i < 8; i++) {
        const int row = m0 + ty * 8 + i;
        if (row >= NN) continue;
        float* outp = g_h + (size_t)row * NC + hop * NHID + tx * 8;
#pragma unroll
        for (int j = 0; j < 8; j++)
            outp[j] = acc[i][j] + bias[hop * NHID + tx * 8 + j];
    }
}

// ---------------------------------------------------------------------------
// SpMM (COO, one hop per launch so the 51.2 MB working set stays L2-resident):
//   agg[row, hop*128 + :] += val * h[col, hop*128 + :]
// One warp per 4 edges; lane handles a float4 (32 lanes * 16B = 512B row slice).
// Vectorized red.global.add.v4.f32 cuts atomic op count 4x vs scalar atomicAdd.
// ---------------------------------------------------------------------------
__global__ __launch_bounds__(256) void spmm(const int* __restrict__ rows,
                                            const int* __restrict__ cols,
                                            const float* __restrict__ vals,
                                            int hop) {
    const int warp = (blockIdx.x * 256 + threadIdx.x) >> 5;
    const int lane = threadIdx.x & 31;
    const int e0 = warp * 4;
    if (e0 >= NE) return;   // NE % 4 == 0, no tail

    const float* hbase = g_h   + hop * NHID + lane * 4;
    float*       abase = g_agg + hop * NHID + lane * 4;

    int r[4], c[4];
    float v[4];
#pragma unroll
    for (int i = 0; i < 4; i++) {
        r[i] = rows[e0 + i];
        c[i] = cols[e0 + i];
        v[i] = vals[e0 + i];
    }

    float4 g[4];
#pragma unroll
    for (int i = 0; i < 4; i++)
        g[i] = *reinterpret_cast<const float4*>(hbase + (size_t)c[i] * NC);

#pragma unroll
    for (int i = 0; i < 4; i++) {
        float* p = abase + (size_t)r[i] * NC;
        asm volatile("red.global.add.v4.f32 [%0], {%1, %2, %3, %4};"
                     :: "l"(p),
                        "f"(v[i] * g[i].x), "f"(v[i] * g[i].y),
                        "f"(v[i] * g[i].z), "f"(v[i] * g[i].w)
                     : "memory");
    }
}

// ---------------------------------------------------------------------------
// GEMM2: y = elu(agg) @ W_out + b_out.  M=50000, K=512, N=64.
// Tile 64x64, BK=16, 256 threads, 4x4 micro-tile. elu fused into A load.
// ---------------------------------------------------------------------------
__device__ __forceinline__ float elu1(float v) {
    return v > 0.f ? v : expm1f(v);
}

__global__ __launch_bounds__(256) void gemm2(const float* __restrict__ Wout,
                                             const float* __restrict__ bout,
                                             float* __restrict__ y) {
    const int m0 = blockIdx.x * 64;

    __shared__ float As[16][64];   // transposed: As[k][m]
    __shared__ float Bs[16][64];   // Bs[k][n]

    const int t  = threadIdx.x;
    const int tx = t & 15;         // n-tile (4 cols)
    const int ty = t >> 4;         // m-tile (4 rows)

    const int a_row = t >> 2;           // 0..63
    const int a_col = (t & 3) * 4;      // 0,4,8,12
    const int b_row = t >> 4;           // 0..15
    const int b_col = (t & 15) * 4;     // 0..60
    const int gr    = m0 + a_row;

    float acc[4][4];
#pragma unroll
    for (int i = 0; i < 4; i++)
#pragma unroll
        for (int j = 0; j < 4; j++) acc[i][j] = 0.f;

    for (int k0 = 0; k0 < NC; k0 += 16) {
        float4 av = make_float4(0.f, 0.f, 0.f, 0.f);
        if (gr < NN)
            av = *reinterpret_cast<const float4*>(g_agg + (size_t)gr * NC + k0 + a_col);
        av.x = elu1(av.x); av.y = elu1(av.y);
        av.z = elu1(av.z); av.w = elu1(av.w);
        const float4 bv =
            *reinterpret_cast<const float4*>(Wout + (size_t)(k0 + b_row) * NO + b_col);

        __syncthreads();
        As[a_col + 0][a_row] = av.x;
        As[a_col + 1][a_row] = av.y;
        As[a_col + 2][a_row] = av.z;
        As[a_col + 3][a_row] = av.w;
        *reinterpret_cast<float4*>(&Bs[b_row][b_col]) = bv;
        __syncthreads();

#pragma unroll
        for (int kk = 0; kk < 16; kk++) {
            float a[4], bb[4];
#pragma unroll
            for (int i = 0; i < 4; i++) a[i] = As[kk][ty * 4 + i];
#pragma unroll
            for (int j = 0; j < 4; j++) bb[j] = Bs[kk][tx * 4 + j];
#pragma unroll
            for (int i = 0; i < 4; i++)
#pragma unroll
                for (int j = 0; j < 4; j++)
                    acc[i][j] = fmaf(a[i], bb[j], acc[i][j]);
        }
    }

#pragma unroll
    for (int i = 0; i < 4; i++) {
        const int row = m0 + ty * 4 + i;
        if (row >= NN) continue;
        float4 o;
        o.x = acc[i][0] + bout[tx * 4 + 0];
        o.y = acc[i][1] + bout[tx * 4 + 1];
        o.z = acc[i][2] + bout[tx * 4 + 2];
        o.w = acc[i][3] + bout[tx * 4 + 3];
        *reinterpret_cast<float4*>(y + (size_t)row * NO + tx * 4) = o;
    }
}

// ---------------------------------------------------------------------------
// Launch. Inputs (metadata order): x, W, b, W_out, b_out, edge_rows,
// edge_cols, edge_vals. Output: [50000, 64] f32.
// ---------------------------------------------------------------------------
extern "C" void kernel_launch(void* const* d_in, const int* in_sizes, int n_in,
                              void* d_out, int out_size) {
    (void)in_sizes; (void)n_in; (void)out_size;
    const float* x     = (const float*)d_in[0];
    const float* W     = (const float*)d_in[1];
    const float* b     = (const float*)d_in[2];
    const float* Wout  = (const float*)d_in[3];
    const float* bout  = (const float*)d_in[4];
    const int*   erows = (const int*)d_in[5];
    const int*   ecols = (const int*)d_in[6];
    const float* evals = (const float*)d_in[7];
    float* y = (float*)d_out;

    zero_agg<<<2048, 256>>>();

    // Fused per-hop linear: h[n, hop*128+j] = x @ W[hop] + b[hop]
    gemm1<<<dim3(KHOP, (NN + 127) / 128), 256>>>(x, W, b);

    // SpMM one hop at a time — keeps the 51.2 MB (h-hop + agg-hop) working
    // set resident in the 126 MB L2 so gathers/atomics never touch HBM.
    const int spmm_blocks = (NE / 4) / 8;   // 4 edges/warp, 8 warps/block
    for (int hop = 0; hop < KHOP; hop++)
        spmm<<<spmm_blocks, 256>>>(erows + (size_t)hop * NE,
                                   ecols + (size_t)hop * NE,
                                   evals + (size_t)hop * NE, hop);

    // elu + output projection
    gemm2<<<(NN + 63) / 64, 256>>>(Wout, bout, y);
}

// round 6
// speedup vs baseline: 1.4481x; 1.4481x over previous
#include <cuda_runtime.h>
#include <cuda_bf16.h>
#include <math.h>
#include <stdint.h>

#define NN   50000
#define NF   256
#define NHID 128
#define KHOP 4
#define NC   512      // KHOP * NHID
#define NE   800000
#define NO   64
#define SA   40       // smem row stride in bf16 elems (80B: 16B-aligned, conflict-free frags)

// ---------------------------------------------------------------------------
// Scratch (__device__ globals per harness allocation rules)
// ---------------------------------------------------------------------------
__device__ float g_h[(size_t)NN * NC];     // post-linear features, hop-blocked cols
__device__ float g_agg[(size_t)NN * NC];   // SpMM accumulator
__device__ __nv_bfloat16 g_xh[(size_t)NN * NF];   // x split-hi
__device__ __nv_bfloat16 g_xl[(size_t)NN * NF];   // x split-lo
__device__ __nv_bfloat16 g_wth[KHOP * NHID * NF]; // W transposed [hop][n][k], hi
__device__ __nv_bfloat16 g_wtl[KHOP * NHID * NF]; // lo
__device__ __nv_bfloat16 g_woth[NO * NC];         // W_out transposed [n][k], hi
__device__ __nv_bfloat16 g_wotl[NO * NC];         // lo

// ---------------------------------------------------------------------------
// mma.sync m16n8k16 bf16 -> f32
// ---------------------------------------------------------------------------
__device__ __forceinline__ void mma16816(float* d, const uint32_t* a, const uint32_t* b) {
    asm volatile(
        "mma.sync.aligned.m16n8k16.row.col.f32.bf16.bf16.f32 "
        "{%0,%1,%2,%3}, {%4,%5,%6,%7}, {%8,%9}, {%0,%1,%2,%3};\n"
        : "+f"(d[0]), "+f"(d[1]), "+f"(d[2]), "+f"(d[3])
        : "r"(a[0]), "r"(a[1]), "r"(a[2]), "r"(a[3]), "r"(b[0]), "r"(b[1]));
}

__device__ __forceinline__ uint32_t lds32(const __nv_bfloat16* p) {
    return *reinterpret_cast<const uint32_t*>(p);
}

__device__ __forceinline__ void split_bf16(float v, __nv_bfloat16& h, __nv_bfloat16& l) {
    h = __float2bfloat16(v);
    l = __float2bfloat16(v - __bfloat162float(h));
}

// ---------------------------------------------------------------------------
// Conversion pre-passes
// ---------------------------------------------------------------------------
__global__ __launch_bounds__(256) void conv_x(const float* __restrict__ x) {
    const size_t n4 = (size_t)NN * NF / 4;
    __nv_bfloat162* ph = reinterpret_cast<__nv_bfloat162*>(g_xh);
    __nv_bfloat162* pl = reinterpret_cast<__nv_bfloat162*>(g_xl);
    for (size_t i = (size_t)blockIdx.x * 256 + threadIdx.x; i < n4;
         i += (size_t)gridDim.x * 256) {
        float4 v = reinterpret_cast<const float4*>(x)[i];
        float vv[4] = {v.x, v.y, v.z, v.w};
        __nv_bfloat16 h[4], l[4];
#pragma unroll
        for (int j = 0; j < 4; j++) split_bf16(vv[j], h[j], l[j]);
        __nv_bfloat162 a, b, c, d;
        a.x = h[0]; a.y = h[1]; b.x = h[2]; b.y = h[3];
        c.x = l[0]; c.y = l[1]; d.x = l[2]; d.y = l[3];
        ph[i * 2] = a; ph[i * 2 + 1] = b;
        pl[i * 2] = c; pl[i * 2 + 1] = d;
    }
}

// W [hop][k][n] -> Wt [hop][n][k], split hi/lo (tiny: 131072 elems)
__global__ __launch_bounds__(256) void conv_w(const float* __restrict__ W) {
    int idx = blockIdx.x * 256 + threadIdx.x;
    if (idx >= KHOP * NF * NHID) return;
    int hop = idx / (NF * NHID);
    int rem = idx - hop * NF * NHID;
    int k = rem / NHID;
    int n = rem - k * NHID;
    __nv_bfloat16 h, l;
    split_bf16(W[idx], h, l);
    size_t o = (size_t)hop * NHID * NF + (size_t)n * NF + k;
    g_wth[o] = h; g_wtl[o] = l;
}

// W_out [k=512][n=64] -> WtO [n][k], split hi/lo (32768 elems)
__global__ __launch_bounds__(256) void conv_wo(const float* __restrict__ Wout) {
    int idx = blockIdx.x * 256 + threadIdx.x;
    if (idx >= NC * NO) return;
    int k = idx / NO;
    int n = idx - k * NO;
    __nv_bfloat16 h, l;
    split_bf16(Wout[idx], h, l);
    g_woth[(size_t)n * NC + k] = h;
    g_wotl[(size_t)n * NC + k] = l;
}

// ---------------------------------------------------------------------------
// Zero the aggregation buffer (atomics accumulate, must re-zero every call)
// ---------------------------------------------------------------------------
__global__ __launch_bounds__(256) void zero_agg() {
    const size_t n4 = (size_t)NN * NC / 4;
    float4* p = reinterpret_cast<float4*>(g_agg);
    const float4 z = make_float4(0.f, 0.f, 0.f, 0.f);
    for (size_t i = (size_t)blockIdx.x * 256 + threadIdx.x; i < n4;
         i += (size_t)gridDim.x * 256)
        p[i] = z;
}

// ---------------------------------------------------------------------------
// GEMM1 (tensor): g_h[n, hop*128+j] = x @ W[hop] + b[hop]
// Split-bf16 3-pass mma: xh*wh + xh*wl + xl*wh, fp32 accumulate.
// CTA tile 128x128, BK=32, 8 warps (4m x 2n), warp tile 32x64.
// ---------------------------------------------------------------------------
__global__ __launch_bounds__(256) void gemm1_mma(const float* __restrict__ bias) {
    const int hop = blockIdx.x;
    const int m0  = blockIdx.y * 128;

    __shared__ __nv_bfloat16 Ash[128 * SA], Asl[128 * SA];
    __shared__ __nv_bfloat16 Bsh[128 * SA], Bsl[128 * SA];

    const int t    = threadIdx.x;
    const int wid  = t >> 5, lane = t & 31;
    const int wm   = wid >> 1, wn = wid & 1;
    const int g    = lane >> 2, t4 = lane & 3;

    // global tile load map: thread covers rows lr and lr+64, 8 bf16 each
    const int lr = t >> 2;          // 0..63
    const int lk = (t & 3) * 8;     // 0,8,16,24

    const __nv_bfloat16* wth = g_wth + (size_t)hop * NHID * NF;
    const __nv_bfloat16* wtl = g_wtl + (size_t)hop * NHID * NF;

    float acc[2][8][4];
#pragma unroll
    for (int i = 0; i < 2; i++)
#pragma unroll
        for (int j = 0; j < 8; j++)
#pragma unroll
            for (int q = 0; q < 4; q++) acc[i][j][q] = 0.f;

    const uint4 z4 = make_uint4(0, 0, 0, 0);
    uint4 pa0, pa1, pal0, pal1, pb0, pb1, pbl0, pbl1;

    const int r0 = m0 + lr, r1 = m0 + lr + 64;
    {   // prefetch k0 = 0
        pa0  = (r0 < NN) ? *(const uint4*)(g_xh + (size_t)r0 * NF + lk) : z4;
        pa1  = (r1 < NN) ? *(const uint4*)(g_xh + (size_t)r1 * NF + lk) : z4;
        pal0 = (r0 < NN) ? *(const uint4*)(g_xl + (size_t)r0 * NF + lk) : z4;
        pal1 = (r1 < NN) ? *(const uint4*)(g_xl + (size_t)r1 * NF + lk) : z4;
        pb0  = *(const uint4*)(wth + (size_t)lr * NF + lk);
        pb1  = *(const uint4*)(wth + (size_t)(lr + 64) * NF + lk);
        pbl0 = *(const uint4*)(wtl + (size_t)lr * NF + lk);
        pbl1 = *(const uint4*)(wtl + (size_t)(lr + 64) * NF + lk);
    }

    for (int k0 = 0; k0 < NF; k0 += 32) {
        __syncthreads();
        *(uint4*)&Ash[lr * SA + lk]        = pa0;
        *(uint4*)&Ash[(lr + 64) * SA + lk] = pa1;
        *(uint4*)&Asl[lr * SA + lk]        = pal0;
        *(uint4*)&Asl[(lr + 64) * SA + lk] = pal1;
        *(uint4*)&Bsh[lr * SA + lk]        = pb0;
        *(uint4*)&Bsh[(lr + 64) * SA + lk] = pb1;
        *(uint4*)&Bsl[lr * SA + lk]        = pbl0;
        *(uint4*)&Bsl[(lr + 64) * SA + lk] = pbl1;
        __syncthreads();

        const int kn = k0 + 32;
        if (kn < NF) {   // prefetch next K-block (overlaps MMA chain below)
            pa0  = (r0 < NN) ? *(const uint4*)(g_xh + (size_t)r0 * NF + kn + lk) : z4;
            pa1  = (r1 < NN) ? *(const uint4*)(g_xh + (size_t)r1 * NF + kn + lk) : z4;
            pal0 = (r0 < NN) ? *(const uint4*)(g_xl + (size_t)r0 * NF + kn + lk) : z4;
            pal1 = (r1 < NN) ? *(const uint4*)(g_xl + (size_t)r1 * NF + kn + lk) : z4;
            pb0  = *(const uint4*)(wth + (size_t)lr * NF + kn + lk);
            pb1  = *(const uint4*)(wth + (size_t)(lr + 64) * NF + kn + lk);
            pbl0 = *(const uint4*)(wtl + (size_t)lr * NF + kn + lk);
            pbl1 = *(const uint4*)(wtl + (size_t)(lr + 64) * NF + kn + lk);
        }

#pragma unroll
        for (int ks = 0; ks < 2; ks++) {
            const int kb = ks * 16 + 2 * t4;
            uint32_t ah[2][4], al[2][4];
#pragma unroll
            for (int mf = 0; mf < 2; mf++) {
                const int rb = (wm * 32 + mf * 16 + g) * SA + kb;
                ah[mf][0] = lds32(&Ash[rb]);
                ah[mf][1] = lds32(&Ash[rb + 8 * SA]);
                ah[mf][2] = lds32(&Ash[rb + 8]);
                ah[mf][3] = lds32(&Ash[rb + 8 * SA + 8]);
                al[mf][0] = lds32(&Asl[rb]);
                al[mf][1] = lds32(&Asl[rb + 8 * SA]);
                al[mf][2] = lds32(&Asl[rb + 8]);
                al[mf][3] = lds32(&Asl[rb + 8 * SA + 8]);
            }
#pragma unroll
            for (int nf = 0; nf < 8; nf++) {
                const int nb = (wn * 64 + nf * 8 + g) * SA + kb;
                uint32_t bh[2], bl[2];
                bh[0] = lds32(&Bsh[nb]); bh[1] = lds32(&Bsh[nb + 8]);
                bl[0] = lds32(&Bsl[nb]); bl[1] = lds32(&Bsl[nb + 8]);
#pragma unroll
                for (int mf = 0; mf < 2; mf++) {
                    mma16816(acc[mf][nf], ah[mf], bh);
                    mma16816(acc[mf][nf], ah[mf], bl);
                    mma16816(acc[mf][nf], al[mf], bh);
                }
            }
        }
    }

    // epilogue: + bias, write hop-blocked cols of g_h
    const int colbase = wn * 64 + 2 * t4;
#pragma unroll
    for (int mf = 0; mf < 2; mf++) {
        const int row = m0 + wm * 32 + mf * 16 + g;
#pragma unroll
        for (int nf = 0; nf < 8; nf++) {
            const int col = colbase + nf * 8;
            const float2 bv = *(const float2*)(bias + hop * NHID + col);
            if (row < NN) {
                float2 o;
                o.x = acc[mf][nf][0] + bv.x;
                o.y = acc[mf][nf][1] + bv.y;
                *(float2*)(g_h + (size_t)row * NC + hop * NHID + col) = o;
            }
            if (row + 8 < NN) {
                float2 o;
                o.x = acc[mf][nf][2] + bv.x;
                o.y = acc[mf][nf][3] + bv.y;
                *(float2*)(g_h + (size_t)(row + 8) * NC + hop * NHID + col) = o;
            }
        }
    }
}

// ---------------------------------------------------------------------------
// SpMM (COO, one hop per launch; per-hop 51.2 MB working set stays L2-resident)
// ---------------------------------------------------------------------------
__global__ __launch_bounds__(256) void spmm(const int* __restrict__ rows,
                                            const int* __restrict__ cols,
                                            const float* __restrict__ vals,
                                            int hop) {
    const int warp = (blockIdx.x * 256 + threadIdx.x) >> 5;
    const int lane = threadIdx.x & 31;
    const int e0 = warp * 4;
    if (e0 >= NE) return;

    const float* hbase = g_h   + hop * NHID + lane * 4;
    float*       abase = g_agg + hop * NHID + lane * 4;

    int r[4], c[4];
    float v[4];
#pragma unroll
    for (int i = 0; i < 4; i++) {
        r[i] = rows[e0 + i];
        c[i] = cols[e0 + i];
        v[i] = vals[e0 + i];
    }

    float4 gv[4];
#pragma unroll
    for (int i = 0; i < 4; i++)
        gv[i] = *reinterpret_cast<const float4*>(hbase + (size_t)c[i] * NC);

#pragma unroll
    for (int i = 0; i < 4; i++) {
        float* p = abase + (size_t)r[i] * NC;
        asm volatile("red.global.add.v4.f32 [%0], {%1, %2, %3, %4};"
                     :: "l"(p),
                        "f"(v[i] * gv[i].x), "f"(v[i] * gv[i].y),
                        "f"(v[i] * gv[i].z), "f"(v[i] * gv[i].w)
                     : "memory");
    }
}

// ---------------------------------------------------------------------------
// GEMM2 (tensor): y = elu(agg) @ W_out + b_out.  M=50000, K=512, N=64.
// elu + split-bf16 fused into the A tile stage. CTA tile 128x64, BK=32.
// 8 warps (4m x 2n), warp tile 32x32.
// ---------------------------------------------------------------------------
__device__ __forceinline__ float elu1(float v) {
    return v > 0.f ? v : (__expf(v) - 1.f);
}

__global__ __launch_bounds__(256) void gemm2_mma(const float* __restrict__ bout,
                                                 float* __restrict__ y) {
    const int m0 = blockIdx.x * 128;

    __shared__ __nv_bfloat16 Ash[128 * SA], Asl[128 * SA];
    __shared__ __nv_bfloat16 Bsh[64 * SA],  Bsl[64 * SA];

    const int t   = threadIdx.x;
    const int wid = t >> 5, lane = t & 31;
    const int wm  = wid >> 1, wn = wid & 1;
    const int g   = lane >> 2, t4 = lane & 3;

    const int ar = t >> 1;          // A row 0..127
    const int ac = (t & 1) * 16;    // A col block (16 f32)
    const int br = t >> 2;          // B row (n) 0..63
    const int bk = (t & 3) * 8;     // B col block (8 bf16)

    const int arow = m0 + ar;
    const bool aok = arow < NN;

    float acc[2][4][4];
#pragma unroll
    for (int i = 0; i < 2; i++)
#pragma unroll
        for (int j = 0; j < 4; j++)
#pragma unroll
            for (int q = 0; q < 4; q++) acc[i][j][q] = 0.f;

    const float4 zf = make_float4(0.f, 0.f, 0.f, 0.f);
    float4 fa[4];
    uint4 pb, pbl;

    {   // prefetch k0 = 0
        const float* ap = g_agg + (size_t)arow * NC + ac;
#pragma unroll
        for (int q = 0; q < 4; q++)
            fa[q] = aok ? *(const float4*)(ap + q * 4) : zf;
        pb  = *(const uint4*)(g_woth + (size_t)br * NC + bk);
        pbl = *(const uint4*)(g_wotl + (size_t)br * NC + bk);
    }

    for (int k0 = 0; k0 < NC; k0 += 32) {
        __syncthreads();
        // elu + split + STS (16 floats -> 2x8 bf16 hi/lo)
#pragma unroll
        for (int q = 0; q < 2; q++) {
            float v[8] = {fa[2*q].x, fa[2*q].y, fa[2*q].z, fa[2*q].w,
                          fa[2*q+1].x, fa[2*q+1].y, fa[2*q+1].z, fa[2*q+1].w};
            union { uint4 u; __nv_bfloat16 b[8]; } uh, ul;
#pragma unroll
            for (int j = 0; j < 8; j++) {
                float e = elu1(v[j]);
                split_bf16(e, uh.b[j], ul.b[j]);
            }
            *(uint4*)&Ash[ar * SA + ac + q * 8] = uh.u;
            *(uint4*)&Asl[ar * SA + ac + q * 8] = ul.u;
        }
        *(uint4*)&Bsh[br * SA + bk] = pb;
        *(uint4*)&Bsl[br * SA + bk] = pbl;
        __syncthreads();

        const int kn = k0 + 32;
        if (kn < NC) {
            const float* ap = g_agg + (size_t)arow * NC + kn + ac;
#pragma unroll
            for (int q = 0; q < 4; q++)
                fa[q] = aok ? *(const float4*)(ap + q * 4) : zf;
            pb  = *(const uint4*)(g_woth + (size_t)br * NC + kn + bk);
            pbl = *(const uint4*)(g_wotl + (size_t)br * NC + kn + bk);
        }

#pragma unroll
        for (int ks = 0; ks < 2; ks++) {
            const int kb = ks * 16 + 2 * t4;
            uint32_t ah[2][4], al[2][4];
#pragma unroll
            for (int mf = 0; mf < 2; mf++) {
                const int rb = (wm * 32 + mf * 16 + g) * SA + kb;
                ah[mf][0] = lds32(&Ash[rb]);
                ah[mf][1] = lds32(&Ash[rb + 8 * SA]);
                ah[mf][2] = lds32(&Ash[rb + 8]);
                ah[mf][3] = lds32(&Ash[rb + 8 * SA + 8]);
                al[mf][0] = lds32(&Asl[rb]);
                al[mf][1] = lds32(&Asl[rb + 8 * SA]);
                al[mf][2] = lds32(&Asl[rb + 8]);
                al[mf][3] = lds32(&Asl[rb + 8 * SA + 8]);
            }
#pragma unroll
            for (int nf = 0; nf < 4; nf++) {
                const int nb = (wn * 32 + nf * 8 + g) * SA + kb;
                uint32_t bh[2], bl[2];
                bh[0] = lds32(&Bsh[nb]); bh[1] = lds32(&Bsh[nb + 8]);
                bl[0] = lds32(&Bsl[nb]); bl[1] = lds32(&Bsl[nb + 8]);
#pragma unroll
                for (int mf = 0; mf < 2; mf++) {
                    mma16816(acc[mf][nf], ah[mf], bh);
                    mma16816(acc[mf][nf], ah[mf], bl);
                    mma16816(acc[mf][nf], al[mf], bh);
                }
            }
        }
    }

    // epilogue: + bout, write y
    const int colbase = wn * 32 + 2 * t4;
#pragma unroll
    for (int mf = 0; mf < 2; mf++) {
        const int row = m0 + wm * 32 + mf * 16 + g;
#pragma unroll
        for (int nf = 0; nf < 4; nf++) {
            const int col = colbase + nf * 8;
            const float2 bv = *(const float2*)(bout + col);
            if (row < NN) {
                float2 o;
                o.x = acc[mf][nf][0] + bv.x;
                o.y = acc[mf][nf][1] + bv.y;
                *(float2*)(y + (size_t)row * NO + col) = o;
            }
            if (row + 8 < NN) {
                float2 o;
                o.x = acc[mf][nf][2] + bv.x;
                o.y = acc[mf][nf][3] + bv.y;
                *(float2*)(y + (size_t)(row + 8) * NO + col) = o;
            }
        }
    }
}

// ---------------------------------------------------------------------------
// Launch. Inputs: x, W, b, W_out, b_out, edge_rows, edge_cols, edge_vals.
// ---------------------------------------------------------------------------
extern "C" void kernel_launch(void* const* d_in, const int* in_sizes, int n_in,
                              void* d_out, int out_size) {
    (void)in_sizes; (void)n_in; (void)out_size;
    const float* x     = (const float*)d_in[0];
    const float* W     = (const float*)d_in[1];
    const float* b     = (const float*)d_in[2];
    const float* Wout  = (const float*)d_in[3];
    const float* bout  = (const float*)d_in[4];
    const int*   erows = (const int*)d_in[5];
    const int*   ecols = (const int*)d_in[6];
    const float* evals = (const float*)d_in[7];
    float* y = (float*)d_out;

    // bf16 hi/lo splits + weight transposes
    conv_x<<<2048, 256>>>(x);
    conv_w<<<(KHOP * NF * NHID + 255) / 256, 256>>>(W);
    conv_wo<<<(NC * NO + 255) / 256, 256>>>(Wout);

    zero_agg<<<2048, 256>>>();

    // per-hop linear on tensor cores (split-bf16, fp32-equivalent accuracy)
    gemm1_mma<<<dim3(KHOP, (NN + 127) / 128), 256>>>(b);

    // SpMM one hop at a time (keeps h-hop + agg-hop L2-resident)
    const int spmm_blocks = (NE / 4) / 8;
    for (int hop = 0; hop < KHOP; hop++)
        spmm<<<spmm_blocks, 256>>>(erows + (size_t)hop * NE,
                                   ecols + (size_t)hop * NE,
                                   evals + (size_t)hop * NE, hop);

    // elu + output projection on tensor cores
    gemm2_mma<<<(NN + 127) / 128, 256>>>(bout, y);
}

// round 7
// speedup vs baseline: 1.7670x; 1.2203x over previous
#include <cuda_runtime.h>
#include <cuda_bf16.h>
#include <math.h>
#include <stdint.h>

#define NN   50000
#define NF   256
#define NHID 128
#define KHOP 4
#define NC   512      // KHOP * NHID
#define NE   800000
#define NO   64
#define SA   40       // smem row stride in bf16 elems (80B, conflict-free frags)

#define NBIN (KHOP * NN)        // 200000 row bins across all hops
#define NET  (KHOP * NE)        // 3200000 edges total
#define SCAN_BLK   256
#define SCAN_PER   16
#define SCAN_CHUNK (SCAN_BLK * SCAN_PER)   // 4096
#define SCAN_NB    49                       // ceil(NBIN / SCAN_CHUNK)

// ---------------------------------------------------------------------------
// Scratch (__device__ globals per harness allocation rules)
// ---------------------------------------------------------------------------
__device__ float g_h[(size_t)NN * NC];     // post-linear features, hop-blocked cols
__device__ float g_agg[(size_t)NN * NC];   // SpMM output (written once per row)
__device__ __nv_bfloat16 g_wth[KHOP * NHID * NF]; // W transposed [hop][n][k], hi
__device__ __nv_bfloat16 g_wtl[KHOP * NHID * NF]; // lo
__device__ __nv_bfloat16 g_woth[NO * NC];         // W_out transposed [n][k], hi
__device__ __nv_bfloat16 g_wotl[NO * NC];         // lo
// CSR build (recomputed every call; deterministic work)
__device__ int   g_cnt[NBIN];
__device__ int   g_rowptr[NBIN + 1];
__device__ int   g_cur[NBIN];
__device__ int   g_bsum[SCAN_NB];
__device__ int   g_scol[NET];
__device__ float g_sval[NET];

// ---------------------------------------------------------------------------
// mma.sync m16n8k16 bf16 -> f32, helpers
// ---------------------------------------------------------------------------
__device__ __forceinline__ void mma16816(float* d, const uint32_t* a, const uint32_t* b) {
    asm volatile(
        "mma.sync.aligned.m16n8k16.row.col.f32.bf16.bf16.f32 "
        "{%0,%1,%2,%3}, {%4,%5,%6,%7}, {%8,%9}, {%0,%1,%2,%3};\n"
        : "+f"(d[0]), "+f"(d[1]), "+f"(d[2]), "+f"(d[3])
        : "r"(a[0]), "r"(a[1]), "r"(a[2]), "r"(a[3]), "r"(b[0]), "r"(b[1]));
}

__device__ __forceinline__ uint32_t lds32(const __nv_bfloat16* p) {
    return *reinterpret_cast<const uint32_t*>(p);
}

__device__ __forceinline__ void split_bf16(float v, __nv_bfloat16& h, __nv_bfloat16& l) {
    h = __float2bfloat16(v);
    l = __float2bfloat16(v - __bfloat162float(h));
}

// split 8 floats (2x float4) into hi/lo bf16 uint4 pair
__device__ __forceinline__ void split8(float4 a, float4 b, uint4& hh, uint4& ll) {
    union { uint4 u; __nv_bfloat16 s[8]; } H, L;
    float v[8] = {a.x, a.y, a.z, a.w, b.x, b.y, b.z, b.w};
#pragma unroll
    for (int j = 0; j < 8; j++) split_bf16(v[j], H.s[j], L.s[j]);
    hh = H.u; ll = L.u;
}

// ---------------------------------------------------------------------------
// Weight conversions (tiny)
// ---------------------------------------------------------------------------
__global__ __launch_bounds__(256) void conv_w(const float* __restrict__ W) {
    int idx = blockIdx.x * 256 + threadIdx.x;
    if (idx >= KHOP * NF * NHID) return;
    int hop = idx / (NF * NHID);
    int rem = idx - hop * NF * NHID;
    int k = rem / NHID;
    int n = rem - k * NHID;
    __nv_bfloat16 h, l;
    split_bf16(W[idx], h, l);
    size_t o = (size_t)hop * NHID * NF + (size_t)n * NF + k;
    g_wth[o] = h; g_wtl[o] = l;
}

__global__ __launch_bounds__(256) void conv_wo(const float* __restrict__ Wout) {
    int idx = blockIdx.x * 256 + threadIdx.x;
    if (idx >= NC * NO) return;
    int k = idx / NO;
    int n = idx - k * NO;
    __nv_bfloat16 h, l;
    split_bf16(Wout[idx], h, l);
    g_woth[(size_t)n * NC + k] = h;
    g_wotl[(size_t)n * NC + k] = l;
}

// ---------------------------------------------------------------------------
// CSR build: zero counts -> histogram -> exclusive scan -> scatter
// Scan is global over all 4 hops: each hop's counts sum to exactly NE, so
// hop h's edges land in g_scol/g_sval[h*NE, (h+1)*NE) automatically.
// ---------------------------------------------------------------------------
__global__ __launch_bounds__(256) void zero_cnt() {
    int i = blockIdx.x * 256 + threadIdx.x;
    if (i < NBIN) g_cnt[i] = 0;
}

__global__ __launch_bounds__(256) void hist(const int* __restrict__ erows) {
    int e = blockIdx.x * 256 + threadIdx.x;
    if (e >= NET) return;
    int hop = e / NE;
    atomicAdd(&g_cnt[hop * NN + erows[e]], 1);
}

__global__ __launch_bounds__(SCAN_BLK) void scan1() {
    __shared__ int sh[SCAN_BLK];
    const int t = threadIdx.x;
    const int base = blockIdx.x * SCAN_CHUNK + t * SCAN_PER;
    int v[SCAN_PER];
    int tot = 0;
#pragma unroll
    for (int i = 0; i < SCAN_PER; i++) {
        v[i] = (base + i < NBIN) ? g_cnt[base + i] : 0;
        tot += v[i];
    }
    sh[t] = tot;
    __syncthreads();
    for (int off = 1; off < SCAN_BLK; off <<= 1) {
        int x = (t >= off) ? sh[t - off] : 0;
        __syncthreads();
        sh[t] += x;
        __syncthreads();
    }
    int excl = sh[t] - tot;
    int run = excl;
#pragma unroll
    for (int i = 0; i < SCAN_PER; i++) {
        if (base + i < NBIN) g_rowptr[base + i] = run;
        run += v[i];
    }
    if (t == 0) g_bsum[blockIdx.x] = sh[SCAN_BLK - 1];
}

__global__ void scan2() {
    if (threadIdx.x == 0) {
        int run = 0;
        for (int b = 0; b < SCAN_NB; b++) {
            int tmp = g_bsum[b];
            g_bsum[b] = run;
            run += tmp;
        }
    }
}

__global__ __launch_bounds__(256) void scan3() {
    int i = blockIdx.x * 256 + threadIdx.x;
    if (i < NBIN) {
        int v = g_rowptr[i] + g_bsum[i / SCAN_CHUNK];
        g_rowptr[i] = v;
        g_cur[i] = v;
    }
    if (i == 0) g_rowptr[NBIN] = NET;
}

__global__ __launch_bounds__(256) void scatter(const int* __restrict__ erows,
                                               const int* __restrict__ ecols,
                                               const float* __restrict__ evals) {
    int e = blockIdx.x * 256 + threadIdx.x;
    if (e >= NET) return;
    int hop = e / NE;
    int pos = atomicAdd(&g_cur[hop * NN + erows[e]], 1);
    g_scol[pos] = ecols[e];
    g_sval[pos] = evals[e];
}

// ---------------------------------------------------------------------------
// GEMM1 (tensor): g_h[n, hop*128+j] = x @ W[hop] + b[hop]
// x split hi/lo in-kernel (no conversion pre-pass). 3-pass split-bf16 mma.
// CTA tile 128x128, BK=32, 8 warps (4m x 2n), warp tile 32x64.
// ---------------------------------------------------------------------------
__global__ __launch_bounds__(256) void gemm1_mma(const float* __restrict__ x,
                                                 const float* __restrict__ bias) {
    const int hop = blockIdx.x;
    const int m0  = blockIdx.y * 128;

    __shared__ __nv_bfloat16 Ash[128 * SA], Asl[128 * SA];
    __shared__ __nv_bfloat16 Bsh[128 * SA], Bsl[128 * SA];

    const int t    = threadIdx.x;
    const int wid  = t >> 5, lane = t & 31;
    const int wm   = wid >> 1, wn = wid & 1;
    const int g    = lane >> 2, t4 = lane & 3;

    const int lr = t >> 2;          // 0..63
    const int lk = (t & 3) * 8;     // 0,8,16,24

    const __nv_bfloat16* wth = g_wth + (size_t)hop * NHID * NF;
    const __nv_bfloat16* wtl = g_wtl + (size_t)hop * NHID * NF;

    float acc[2][8][4];
#pragma unroll
    for (int i = 0; i < 2; i++)
#pragma unroll
        for (int j = 0; j < 8; j++)
#pragma unroll
            for (int q = 0; q < 4; q++) acc[i][j][q] = 0.f;

    const float4 zf = make_float4(0.f, 0.f, 0.f, 0.f);
    float4 fx0a, fx0b, fx1a, fx1b;
    uint4 pb0, pb1, pbl0, pbl1;

    const int r0 = m0 + lr, r1 = m0 + lr + 64;
    {   // prefetch k0 = 0
        fx0a = (r0 < NN) ? *(const float4*)(x + (size_t)r0 * NF + lk)     : zf;
        fx0b = (r0 < NN) ? *(const float4*)(x + (size_t)r0 * NF + lk + 4) : zf;
        fx1a = (r1 < NN) ? *(const float4*)(x + (size_t)r1 * NF + lk)     : zf;
        fx1b = (r1 < NN) ? *(const float4*)(x + (size_t)r1 * NF + lk + 4) : zf;
        pb0  = *(const uint4*)(wth + (size_t)lr * NF + lk);
        pb1  = *(const uint4*)(wth + (size_t)(lr + 64) * NF + lk);
        pbl0 = *(const uint4*)(wtl + (size_t)lr * NF + lk);
        pbl1 = *(const uint4*)(wtl + (size_t)(lr + 64) * NF + lk);
    }

    for (int k0 = 0; k0 < NF; k0 += 32) {
        __syncthreads();
        {
            uint4 hh, ll;
            split8(fx0a, fx0b, hh, ll);
            *(uint4*)&Ash[lr * SA + lk] = hh;
            *(uint4*)&Asl[lr * SA + lk] = ll;
            split8(fx1a, fx1b, hh, ll);
            *(uint4*)&Ash[(lr + 64) * SA + lk] = hh;
            *(uint4*)&Asl[(lr + 64) * SA + lk] = ll;
        }
        *(uint4*)&Bsh[lr * SA + lk]        = pb0;
        *(uint4*)&Bsh[(lr + 64) * SA + lk] = pb1;
        *(uint4*)&Bsl[lr * SA + lk]        = pbl0;
        *(uint4*)&Bsl[(lr + 64) * SA + lk] = pbl1;
        __syncthreads();

        const int kn = k0 + 32;
        if (kn < NF) {   // prefetch next K-block
            fx0a = (r0 < NN) ? *(const float4*)(x + (size_t)r0 * NF + kn + lk)     : zf;
            fx0b = (r0 < NN) ? *(const float4*)(x + (size_t)r0 * NF + kn + lk + 4) : zf;
            fx1a = (r1 < NN) ? *(const float4*)(x + (size_t)r1 * NF + kn + lk)     : zf;
            fx1b = (r1 < NN) ? *(const float4*)(x + (size_t)r1 * NF + kn + lk + 4) : zf;
            pb0  = *(const uint4*)(wth + (size_t)lr * NF + kn + lk);
            pb1  = *(const uint4*)(wth + (size_t)(lr + 64) * NF + kn + lk);
            pbl0 = *(const uint4*)(wtl + (size_t)lr * NF + kn + lk);
            pbl1 = *(const uint4*)(wtl + (size_t)(lr + 64) * NF + kn + lk);
        }

#pragma unroll
        for (int ks = 0; ks < 2; ks++) {
            const int kb = ks * 16 + 2 * t4;
            uint32_t ah[2][4], al[2][4];
#pragma unroll
            for (int mf = 0; mf < 2; mf++) {
                const int rb = (wm * 32 + mf * 16 + g) * SA + kb;
                ah[mf][0] = lds32(&Ash[rb]);
                ah[mf][1] = lds32(&Ash[rb + 8 * SA]);
                ah[mf][2] = lds32(&Ash[rb + 8]);
                ah[mf][3] = lds32(&Ash[rb + 8 * SA + 8]);
                al[mf][0] = lds32(&Asl[rb]);
                al[mf][1] = lds32(&Asl[rb + 8 * SA]);
                al[mf][2] = lds32(&Asl[rb + 8]);
                al[mf][3] = lds32(&Asl[rb + 8 * SA + 8]);
            }
#pragma unroll
            for (int nf = 0; nf < 8; nf++) {
                const int nb = (wn * 64 + nf * 8 + g) * SA + kb;
                uint32_t bh[2], bl[2];
                bh[0] = lds32(&Bsh[nb]); bh[1] = lds32(&Bsh[nb + 8]);
                bl[0] = lds32(&Bsl[nb]); bl[1] = lds32(&Bsl[nb + 8]);
#pragma unroll
                for (int mf = 0; mf < 2; mf++) {
                    mma16816(acc[mf][nf], ah[mf], bh);
                    mma16816(acc[mf][nf], ah[mf], bl);
                    mma16816(acc[mf][nf], al[mf], bh);
                }
            }
        }
    }

    const int colbase = wn * 64 + 2 * t4;
#pragma unroll
    for (int mf = 0; mf < 2; mf++) {
        const int row = m0 + wm * 32 + mf * 16 + g;
#pragma unroll
        for (int nf = 0; nf < 8; nf++) {
            const int col = colbase + nf * 8;
            const float2 bv = *(const float2*)(bias + hop * NHID + col);
            if (row < NN) {
                float2 o;
                o.x = acc[mf][nf][0] + bv.x;
                o.y = acc[mf][nf][1] + bv.y;
                *(float2*)(g_h + (size_t)row * NC + hop * NHID + col) = o;
            }
            if (row + 8 < NN) {
                float2 o;
                o.x = acc[mf][nf][2] + bv.x;
                o.y = acc[mf][nf][3] + bv.y;
                *(float2*)(g_h + (size_t)(row + 8) * NC + hop * NHID + col) = o;
            }
        }
    }
}

// ---------------------------------------------------------------------------
// CSR SpMM: one warp per output row, register accumulation, single write.
// Lane owns a float4 slice (32 x 16B = 512B row). Gathers unrolled 4-wide
// for MLP. Rows with no edges write zeros (replaces zero_agg).
// One hop per launch keeps the 51.2 MB (h-hop + agg-hop) set L2-resident.
// ---------------------------------------------------------------------------
__global__ __launch_bounds__(256) void spmm_csr(int hop) {
    const int row  = (blockIdx.x * 256 + threadIdx.x) >> 5;
    const int lane = threadIdx.x & 31;
    if (row >= NN) return;

    const int bin = hop * NN + row;
    const int s = g_rowptr[bin];
    const int e = g_rowptr[bin + 1];

    const float* hb = g_h + hop * NHID + lane * 4;
    float4 acc = make_float4(0.f, 0.f, 0.f, 0.f);

    for (int p = s; p < e; p += 32) {
        const int n = min(32, e - p);
        const int  c = (lane < n) ? g_scol[p + lane] : 0;
        const float v = (lane < n) ? g_sval[p + lane] : 0.f;
        int j = 0;
        for (; j + 4 <= n; j += 4) {
            int   c0 = __shfl_sync(0xffffffffu, c, j);
            int   c1 = __shfl_sync(0xffffffffu, c, j + 1);
            int   c2 = __shfl_sync(0xffffffffu, c, j + 2);
            int   c3 = __shfl_sync(0xffffffffu, c, j + 3);
            float v0 = __shfl_sync(0xffffffffu, v, j);
            float v1 = __shfl_sync(0xffffffffu, v, j + 1);
            float v2 = __shfl_sync(0xffffffffu, v, j + 2);
            float v3 = __shfl_sync(0xffffffffu, v, j + 3);
            float4 g0 = *(const float4*)(hb + (size_t)c0 * NC);
            float4 g1 = *(const float4*)(hb + (size_t)c1 * NC);
            float4 g2 = *(const float4*)(hb + (size_t)c2 * NC);
            float4 g3 = *(const float4*)(hb + (size_t)c3 * NC);
            acc.x = fmaf(v0, g0.x, acc.x); acc.y = fmaf(v0, g0.y, acc.y);
            acc.z = fmaf(v0, g0.z, acc.z); acc.w = fmaf(v0, g0.w, acc.w);
            acc.x = fmaf(v1, g1.x, acc.x); acc.y = fmaf(v1, g1.y, acc.y);
            acc.z = fmaf(v1, g1.z, acc.z); acc.w = fmaf(v1, g1.w, acc.w);
            acc.x = fmaf(v2, g2.x, acc.x); acc.y = fmaf(v2, g2.y, acc.y);
            acc.z = fmaf(v2, g2.z, acc.z); acc.w = fmaf(v2, g2.w, acc.w);
            acc.x = fmaf(v3, g3.x, acc.x); acc.y = fmaf(v3, g3.y, acc.y);
            acc.z = fmaf(v3, g3.z, acc.z); acc.w = fmaf(v3, g3.w, acc.w);
        }
        for (; j < n; j++) {
            int   cj = __shfl_sync(0xffffffffu, c, j);
            float vj = __shfl_sync(0xffffffffu, v, j);
            float4 gj = *(const float4*)(hb + (size_t)cj * NC);
            acc.x = fmaf(vj, gj.x, acc.x); acc.y = fmaf(vj, gj.y, acc.y);
            acc.z = fmaf(vj, gj.z, acc.z); acc.w = fmaf(vj, gj.w, acc.w);
        }
    }

    *(float4*)(g_agg + (size_t)row * NC + hop * NHID + lane * 4) = acc;
}

// ---------------------------------------------------------------------------
// GEMM2 (tensor): y = elu(agg) @ W_out + b_out.  elu + split fused in A stage.
// CTA tile 128x64, BK=32, 8 warps (4m x 2n), warp tile 32x32.
// ---------------------------------------------------------------------------
__device__ __forceinline__ float elu1(float v) {
    return v > 0.f ? v : (__expf(v) - 1.f);
}

__global__ __launch_bounds__(256) void gemm2_mma(const float* __restrict__ bout,
                                                 float* __restrict__ y) {
    const int m0 = blockIdx.x * 128;

    __shared__ __nv_bfloat16 Ash[128 * SA], Asl[128 * SA];
    __shared__ __nv_bfloat16 Bsh[64 * SA],  Bsl[64 * SA];

    const int t   = threadIdx.x;
    const int wid = t >> 5, lane = t & 31;
    const int wm  = wid >> 1, wn = wid & 1;
    const int g   = lane >> 2, t4 = lane & 3;

    const int ar = t >> 1;          // A row 0..127
    const int ac = (t & 1) * 16;    // A col block (16 f32)
    const int br = t >> 2;          // B row (n) 0..63
    const int bk = (t & 3) * 8;     // B col block (8 bf16)

    const int arow = m0 + ar;
    const bool aok = arow < NN;

    float acc[2][4][4];
#pragma unroll
    for (int i = 0; i < 2; i++)
#pragma unroll
        for (int j = 0; j < 4; j++)
#pragma unroll
            for (int q = 0; q < 4; q++) acc[i][j][q] = 0.f;

    const float4 zf = make_float4(0.f, 0.f, 0.f, 0.f);
    float4 fa[4];
    uint4 pb, pbl;

    {
        const float* ap = g_agg + (size_t)arow * NC + ac;
#pragma unroll
        for (int q = 0; q < 4; q++)
            fa[q] = aok ? *(const float4*)(ap + q * 4) : zf;
        pb  = *(const uint4*)(g_woth + (size_t)br * NC + bk);
        pbl = *(const uint4*)(g_wotl + (size_t)br * NC + bk);
    }

    for (int k0 = 0; k0 < NC; k0 += 32) {
        __syncthreads();
#pragma unroll
        for (int q = 0; q < 2; q++) {
            float v[8] = {fa[2*q].x, fa[2*q].y, fa[2*q].z, fa[2*q].w,
                          fa[2*q+1].x, fa[2*q+1].y, fa[2*q+1].z, fa[2*q+1].w};
            union { uint4 u; __nv_bfloat16 b[8]; } uh, ul;
#pragma unroll
            for (int j = 0; j < 8; j++) {
                float e = elu1(v[j]);
                split_bf16(e, uh.b[j], ul.b[j]);
            }
            *(uint4*)&Ash[ar * SA + ac + q * 8] = uh.u;
            *(uint4*)&Asl[ar * SA + ac + q * 8] = ul.u;
        }
        *(uint4*)&Bsh[br * SA + bk] = pb;
        *(uint4*)&Bsl[br * SA + bk] = pbl;
        __syncthreads();

        const int kn = k0 + 32;
        if (kn < NC) {
            const float* ap = g_agg + (size_t)arow * NC + kn + ac;
#pragma unroll
            for (int q = 0; q < 4; q++)
                fa[q] = aok ? *(const float4*)(ap + q * 4) : zf;
            pb  = *(const uint4*)(g_woth + (size_t)br * NC + kn + bk);
            pbl = *(const uint4*)(g_wotl + (size_t)br * NC + kn + bk);
        }

#pragma unroll
        for (int ks = 0; ks < 2; ks++) {
            const int kb = ks * 16 + 2 * t4;
            uint32_t ah[2][4], al[2][4];
#pragma unroll
            for (int mf = 0; mf < 2; mf++) {
                const int rb = (wm * 32 + mf * 16 + g) * SA + kb;
                ah[mf][0] = lds32(&Ash[rb]);
                ah[mf][1] = lds32(&Ash[rb + 8 * SA]);
                ah[mf][2] = lds32(&Ash[rb + 8]);
                ah[mf][3] = lds32(&Ash[rb + 8 * SA + 8]);
                al[mf][0] = lds32(&Asl[rb]);
                al[mf][1] = lds32(&Asl[rb + 8 * SA]);
                al[mf][2] = lds32(&Asl[rb + 8]);
                al[mf][3] = lds32(&Asl[rb + 8 * SA + 8]);
            }
#pragma unroll
            for (int nf = 0; nf < 4; nf++) {
                const int nb = (wn * 32 + nf * 8 + g) * SA + kb;
                uint32_t bh[2], bl[2];
                bh[0] = lds32(&Bsh[nb]); bh[1] = lds32(&Bsh[nb + 8]);
                bl[0] = lds32(&Bsl[nb]); bl[1] = lds32(&Bsl[nb + 8]);
#pragma unroll
                for (int mf = 0; mf < 2; mf++) {
                    mma16816(acc[mf][nf], ah[mf], bh);
                    mma16816(acc[mf][nf], ah[mf], bl);
                    mma16816(acc[mf][nf], al[mf], bh);
                }
            }
        }
    }

    const int colbase = wn * 32 + 2 * t4;
#pragma unroll
    for (int mf = 0; mf < 2; mf++) {
        const int row = m0 + wm * 32 + mf * 16 + g;
#pragma unroll
        for (int nf = 0; nf < 4; nf++) {
            const int col = colbase + nf * 8;
            const float2 bv = *(const float2*)(bout + col);
            if (row < NN) {
                float2 o;
                o.x = acc[mf][nf][0] + bv.x;
                o.y = acc[mf][nf][1] + bv.y;
                *(float2*)(y + (size_t)row * NO + col) = o;
            }
            if (row + 8 < NN) {
                float2 o;
                o.x = acc[mf][nf][2] + bv.x;
                o.y = acc[mf][nf][3] + bv.y;
                *(float2*)(y + (size_t)(row + 8) * NO + col) = o;
            }
        }
    }
}

// ---------------------------------------------------------------------------
// Launch. Inputs: x, W, b, W_out, b_out, edge_rows, edge_cols, edge_vals.
// ---------------------------------------------------------------------------
extern "C" void kernel_launch(void* const* d_in, const int* in_sizes, int n_in,
                              void* d_out, int out_size) {
    (void)in_sizes; (void)n_in; (void)out_size;
    const float* x     = (const float*)d_in[0];
    const float* W     = (const float*)d_in[1];
    const float* b     = (const float*)d_in[2];
    const float* Wout  = (const float*)d_in[3];
    const float* bout  = (const float*)d_in[4];
    const int*   erows = (const int*)d_in[5];
    const int*   ecols = (const int*)d_in[6];
    const float* evals = (const float*)d_in[7];
    float* y = (float*)d_out;

    // CSR build (hist -> scan -> scatter), all hops at once
    zero_cnt<<<(NBIN + 255) / 256, 256>>>();
    hist<<<NET / 256, 256>>>(erows);
    scan1<<<SCAN_NB, SCAN_BLK>>>();
    scan2<<<1, 32>>>();
    scan3<<<(NBIN + 255) / 256, 256>>>();
    scatter<<<NET / 256, 256>>>(erows, ecols, evals);

    // weight splits/transposes (tiny)
    conv_w<<<(KHOP * NF * NHID + 255) / 256, 256>>>(W);
    conv_wo<<<(NC * NO + 255) / 256, 256>>>(Wout);

    // per-hop linear on tensor cores (x split in-kernel)
    gemm1_mma<<<dim3(KHOP, (NN + 127) / 128), 256>>>(x, b);

    // CSR SpMM, one hop at a time (L2-resident working set), rows written once
    const int spmm_blocks = (NN * 32 + 255) / 256;   // 1 warp / row
    for (int hop = 0; hop < KHOP; hop++)
        spmm_csr<<<spmm_blocks, 256>>>(hop);

    // elu + output projection on tensor cores
    gemm2_mma<<<(NN + 127) / 128, 256>>>(bout, y);
}

// round 8
// speedup vs baseline: 2.0808x; 1.1776x over previous
#include <cuda_runtime.h>
#include <cuda_bf16.h>
#include <cuda_fp16.h>
#include <math.h>
#include <stdint.h>

#define NN   50000
#define NF   256
#define NHID 128
#define KHOP 4
#define NC   512      // KHOP * NHID
#define NE   800000
#define NO   64
#define SA   40       // smem row stride in bf16 elems (80B, conflict-free frags)

#define NBIN (KHOP * NN)        // 200000 row bins across all hops
#define NET  (KHOP * NE)        // 3200000 edges total
#define SCAN_BLK   256
#define SCAN_PER   16
#define SCAN_CHUNK (SCAN_BLK * SCAN_PER)   // 4096
#define SCAN_NB    49                       // ceil(NBIN / SCAN_CHUNK)

// ---------------------------------------------------------------------------
// Scratch (__device__ globals per harness allocation rules)
// ---------------------------------------------------------------------------
__device__ __half g_h[(size_t)NN * NC];    // post-linear features (fp16: halves
                                           // spmm gather traffic; 51.2MB total
                                           // -> whole 4-hop set is L2-resident)
__device__ float  g_agg[(size_t)NN * NC];  // SpMM output, fp32 (written once)
__device__ __nv_bfloat16 g_wth[KHOP * NHID * NF]; // W transposed [hop][n][k], hi
__device__ __nv_bfloat16 g_wtl[KHOP * NHID * NF]; // lo
__device__ __nv_bfloat16 g_woth[NO * NC];         // W_out transposed [n][k], hi
__device__ __nv_bfloat16 g_wotl[NO * NC];         // lo
// CSR build (recomputed every call; deterministic work)
__device__ int   g_cnt[NBIN];
__device__ int   g_rowptr[NBIN + 1];
__device__ int   g_cur[NBIN];
__device__ int   g_bsum[SCAN_NB];
__device__ int   g_scol[NET];
__device__ float g_sval[NET];

// ---------------------------------------------------------------------------
// mma.sync m16n8k16 bf16 -> f32, helpers
// ---------------------------------------------------------------------------
__device__ __forceinline__ void mma16816(float* d, const uint32_t* a, const uint32_t* b) {
    asm volatile(
        "mma.sync.aligned.m16n8k16.row.col.f32.bf16.bf16.f32 "
        "{%0,%1,%2,%3}, {%4,%5,%6,%7}, {%8,%9}, {%0,%1,%2,%3};\n"
        : "+f"(d[0]), "+f"(d[1]), "+f"(d[2]), "+f"(d[3])
        : "r"(a[0]), "r"(a[1]), "r"(a[2]), "r"(a[3]), "r"(b[0]), "r"(b[1]));
}

__device__ __forceinline__ uint32_t lds32(const __nv_bfloat16* p) {
    return *reinterpret_cast<const uint32_t*>(p);
}

__device__ __forceinline__ void split_bf16(float v, __nv_bfloat16& h, __nv_bfloat16& l) {
    h = __float2bfloat16(v);
    l = __float2bfloat16(v - __bfloat162float(h));
}

__device__ __forceinline__ void split8(float4 a, float4 b, uint4& hh, uint4& ll) {
    union { uint4 u; __nv_bfloat16 s[8]; } H, L;
    float v[8] = {a.x, a.y, a.z, a.w, b.x, b.y, b.z, b.w};
#pragma unroll
    for (int j = 0; j < 8; j++) split_bf16(v[j], H.s[j], L.s[j]);
    hh = H.u; ll = L.u;
}

// ---------------------------------------------------------------------------
// Prep: zero CSR counters + both weight split/transposes, one kernel.
// ---------------------------------------------------------------------------
__global__ __launch_bounds__(256) void prep(const float* __restrict__ W,
                                            const float* __restrict__ Wout) {
    const int idx = blockIdx.x * 256 + threadIdx.x;
    if (idx < NBIN) g_cnt[idx] = 0;
    if (idx < KHOP * NF * NHID) {
        int hop = idx / (NF * NHID);
        int rem = idx - hop * (NF * NHID);
        int k = rem / NHID;
        int n = rem - k * NHID;
        __nv_bfloat16 h, l;
        split_bf16(W[idx], h, l);
        size_t o = (size_t)hop * NHID * NF + (size_t)n * NF + k;
        g_wth[o] = h; g_wtl[o] = l;
    }
    if (idx < NC * NO) {
        int k = idx / NO;
        int n = idx - k * NO;
        __nv_bfloat16 h, l;
        split_bf16(Wout[idx], h, l);
        g_woth[(size_t)n * NC + k] = h;
        g_wotl[(size_t)n * NC + k] = l;
    }
}

// ---------------------------------------------------------------------------
// CSR build: histogram -> two-level scan -> scatter. Scan is global across
// hops (each hop sums to exactly NE, so hop h lands in [h*NE, (h+1)*NE)).
// ---------------------------------------------------------------------------
__global__ __launch_bounds__(256) void hist(const int* __restrict__ erows) {
    int e = blockIdx.x * 256 + threadIdx.x;
    if (e >= NET) return;
    int hop = e / NE;
    atomicAdd(&g_cnt[hop * NN + erows[e]], 1);
}

__global__ __launch_bounds__(SCAN_BLK) void scan1() {
    __shared__ int sh[SCAN_BLK];
    const int t = threadIdx.x;
    const int base = blockIdx.x * SCAN_CHUNK + t * SCAN_PER;
    int v[SCAN_PER];
    int tot = 0;
#pragma unroll
    for (int i = 0; i < SCAN_PER; i++) {
        v[i] = (base + i < NBIN) ? g_cnt[base + i] : 0;
        tot += v[i];
    }
    sh[t] = tot;
    __syncthreads();
    for (int off = 1; off < SCAN_BLK; off <<= 1) {
        int x = (t >= off) ? sh[t - off] : 0;
        __syncthreads();
        sh[t] += x;
        __syncthreads();
    }
    int run = sh[t] - tot;
#pragma unroll
    for (int i = 0; i < SCAN_PER; i++) {
        if (base + i < NBIN) g_rowptr[base + i] = run;
        run += v[i];
    }
    if (t == 0) g_bsum[blockIdx.x] = sh[SCAN_BLK - 1];
}

// adds block-prefix (summing <=48 cached g_bsum entries per thread; removes
// the serial scan2 kernel) and seeds g_cur.
__global__ __launch_bounds__(256) void scan3() {
    int i = blockIdx.x * 256 + threadIdx.x;
    if (i < NBIN) {
        const int nb = i / SCAN_CHUNK;
        int pre = 0;
        for (int b = 0; b < nb; b++) pre += g_bsum[b];
        int v = g_rowptr[i] + pre;
        g_rowptr[i] = v;
        g_cur[i] = v;
    }
    if (i == 0) g_rowptr[NBIN] = NET;
}

__global__ __launch_bounds__(256) void scatter(const int* __restrict__ erows,
                                               const int* __restrict__ ecols,
                                               const float* __restrict__ evals) {
    int e = blockIdx.x * 256 + threadIdx.x;
    if (e >= NET) return;
    int hop = e / NE;
    int pos = atomicAdd(&g_cur[hop * NN + erows[e]], 1);
    g_scol[pos] = ecols[e];
    g_sval[pos] = evals[e];
}

// ---------------------------------------------------------------------------
// GEMM1 (tensor): g_h[n, hop*128+j] = fp16(x @ W[hop] + b[hop])
// x split hi/lo in-kernel. 3-pass split-bf16 mma, fp32 accumulate.
// CTA tile 128x128, BK=32, 8 warps (4m x 2n), warp tile 32x64.
// ---------------------------------------------------------------------------
__global__ __launch_bounds__(256) void gemm1_mma(const float* __restrict__ x,
                                                 const float* __restrict__ bias) {
    const int hop = blockIdx.x;
    const int m0  = blockIdx.y * 128;

    __shared__ __nv_bfloat16 Ash[128 * SA], Asl[128 * SA];
    __shared__ __nv_bfloat16 Bsh[128 * SA], Bsl[128 * SA];

    const int t    = threadIdx.x;
    const int wid  = t >> 5, lane = t & 31;
    const int wm   = wid >> 1, wn = wid & 1;
    const int g    = lane >> 2, t4 = lane & 3;

    const int lr = t >> 2;          // 0..63
    const int lk = (t & 3) * 8;     // 0,8,16,24

    const __nv_bfloat16* wth = g_wth + (size_t)hop * NHID * NF;
    const __nv_bfloat16* wtl = g_wtl + (size_t)hop * NHID * NF;

    float acc[2][8][4];
#pragma unroll
    for (int i = 0; i < 2; i++)
#pragma unroll
        for (int j = 0; j < 8; j++)
#pragma unroll
            for (int q = 0; q < 4; q++) acc[i][j][q] = 0.f;

    const float4 zf = make_float4(0.f, 0.f, 0.f, 0.f);
    float4 fx0a, fx0b, fx1a, fx1b;
    uint4 pb0, pb1, pbl0, pbl1;

    const int r0 = m0 + lr, r1 = m0 + lr + 64;
    {   // prefetch k0 = 0
        fx0a = (r0 < NN) ? *(const float4*)(x + (size_t)r0 * NF + lk)     : zf;
        fx0b = (r0 < NN) ? *(const float4*)(x + (size_t)r0 * NF + lk + 4) : zf;
        fx1a = (r1 < NN) ? *(const float4*)(x + (size_t)r1 * NF + lk)     : zf;
        fx1b = (r1 < NN) ? *(const float4*)(x + (size_t)r1 * NF + lk + 4) : zf;
        pb0  = *(const uint4*)(wth + (size_t)lr * NF + lk);
        pb1  = *(const uint4*)(wth + (size_t)(lr + 64) * NF + lk);
        pbl0 = *(const uint4*)(wtl + (size_t)lr * NF + lk);
        pbl1 = *(const uint4*)(wtl + (size_t)(lr + 64) * NF + lk);
    }

    for (int k0 = 0; k0 < NF; k0 += 32) {
        __syncthreads();
        {
            uint4 hh, ll;
            split8(fx0a, fx0b, hh, ll);
            *(uint4*)&Ash[lr * SA + lk] = hh;
            *(uint4*)&Asl[lr * SA + lk] = ll;
            split8(fx1a, fx1b, hh, ll);
            *(uint4*)&Ash[(lr + 64) * SA + lk] = hh;
            *(uint4*)&Asl[(lr + 64) * SA + lk] = ll;
        }
        *(uint4*)&Bsh[lr * SA + lk]        = pb0;
        *(uint4*)&Bsh[(lr + 64) * SA + lk] = pb1;
        *(uint4*)&Bsl[lr * SA + lk]        = pbl0;
        *(uint4*)&Bsl[(lr + 64) * SA + lk] = pbl1;
        __syncthreads();

        const int kn = k0 + 32;
        if (kn < NF) {   // prefetch next K-block
            fx0a = (r0 < NN) ? *(const float4*)(x + (size_t)r0 * NF + kn + lk)     : zf;
            fx0b = (r0 < NN) ? *(const float4*)(x + (size_t)r0 * NF + kn + lk + 4) : zf;
            fx1a = (r1 < NN) ? *(const float4*)(x + (size_t)r1 * NF + kn + lk)     : zf;
            fx1b = (r1 < NN) ? *(const float4*)(x + (size_t)r1 * NF + kn + lk + 4) : zf;
            pb0  = *(const uint4*)(wth + (size_t)lr * NF + kn + lk);
            pb1  = *(const uint4*)(wth + (size_t)(lr + 64) * NF + kn + lk);
            pbl0 = *(const uint4*)(wtl + (size_t)lr * NF + kn + lk);
            pbl1 = *(const uint4*)(wtl + (size_t)(lr + 64) * NF + kn + lk);
        }

#pragma unroll
        for (int ks = 0; ks < 2; ks++) {
            const int kb = ks * 16 + 2 * t4;
            uint32_t ah[2][4], al[2][4];
#pragma unroll
            for (int mf = 0; mf < 2; mf++) {
                const int rb = (wm * 32 + mf * 16 + g) * SA + kb;
                ah[mf][0] = lds32(&Ash[rb]);
                ah[mf][1] = lds32(&Ash[rb + 8 * SA]);
                ah[mf][2] = lds32(&Ash[rb + 8]);
                ah[mf][3] = lds32(&Ash[rb + 8 * SA + 8]);
                al[mf][0] = lds32(&Asl[rb]);
                al[mf][1] = lds32(&Asl[rb + 8 * SA]);
                al[mf][2] = lds32(&Asl[rb + 8]);
                al[mf][3] = lds32(&Asl[rb + 8 * SA + 8]);
            }
#pragma unroll
            for (int nf = 0; nf < 8; nf++) {
                const int nb = (wn * 64 + nf * 8 + g) * SA + kb;
                uint32_t bh[2], bl[2];
                bh[0] = lds32(&Bsh[nb]); bh[1] = lds32(&Bsh[nb + 8]);
                bl[0] = lds32(&Bsl[nb]); bl[1] = lds32(&Bsl[nb + 8]);
#pragma unroll
                for (int mf = 0; mf < 2; mf++) {
                    mma16816(acc[mf][nf], ah[mf], bh);
                    mma16816(acc[mf][nf], ah[mf], bl);
                    mma16816(acc[mf][nf], al[mf], bh);
                }
            }
        }
    }

    const int colbase = wn * 64 + 2 * t4;
#pragma unroll
    for (int mf = 0; mf < 2; mf++) {
        const int row = m0 + wm * 32 + mf * 16 + g;
#pragma unroll
        for (int nf = 0; nf < 8; nf++) {
            const int col = colbase + nf * 8;
            const float2 bv = *(const float2*)(bias + hop * NHID + col);
            if (row < NN) {
                *(__half2*)(g_h + (size_t)row * NC + hop * NHID + col) =
                    __floats2half2_rn(acc[mf][nf][0] + bv.x, acc[mf][nf][1] + bv.y);
            }
            if (row + 8 < NN) {
                *(__half2*)(g_h + (size_t)(row + 8) * NC + hop * NHID + col) =
                    __floats2half2_rn(acc[mf][nf][2] + bv.x, acc[mf][nf][3] + bv.y);
            }
        }
    }
}

// ---------------------------------------------------------------------------
// CSR SpMM, all hops in one launch (fp16 h: whole 51.2MB set is L2-resident;
// blockIdx.x-fastest scheduling keeps per-hop locality). One warp per row,
// fp32 register accumulation, single fp32 write. Lane owns 4 features (8B
// fp16 gather per edge). Gathers unrolled 4-wide for MLP.
// ---------------------------------------------------------------------------
__global__ __launch_bounds__(256) void spmm_csr() {
    const int row  = (blockIdx.x * 256 + threadIdx.x) >> 5;
    const int lane = threadIdx.x & 31;
    if (row >= NN) return;
    const int hop = blockIdx.y;

    const int bin = hop * NN + row;
    const int s = g_rowptr[bin];
    const int e = g_rowptr[bin + 1];

    const __half* hb = g_h + hop * NHID + lane * 4;
    float4 acc = make_float4(0.f, 0.f, 0.f, 0.f);

    for (int p = s; p < e; p += 32) {
        const int n = min(32, e - p);
        const int  c = (lane < n) ? g_scol[p + lane] : 0;
        const float v = (lane < n) ? g_sval[p + lane] : 0.f;
        int j = 0;
        for (; j + 4 <= n; j += 4) {
            int   c0 = __shfl_sync(0xffffffffu, c, j);
            int   c1 = __shfl_sync(0xffffffffu, c, j + 1);
            int   c2 = __shfl_sync(0xffffffffu, c, j + 2);
            int   c3 = __shfl_sync(0xffffffffu, c, j + 3);
            float v0 = __shfl_sync(0xffffffffu, v, j);
            float v1 = __shfl_sync(0xffffffffu, v, j + 1);
            float v2 = __shfl_sync(0xffffffffu, v, j + 2);
            float v3 = __shfl_sync(0xffffffffu, v, j + 3);
            uint2 u0 = *(const uint2*)(hb + (size_t)c0 * NC);
            uint2 u1 = *(const uint2*)(hb + (size_t)c1 * NC);
            uint2 u2 = *(const uint2*)(hb + (size_t)c2 * NC);
            uint2 u3 = *(const uint2*)(hb + (size_t)c3 * NC);
            float2 a0 = __half22float2(*(__half2*)&u0.x);
            float2 b0 = __half22float2(*(__half2*)&u0.y);
            float2 a1 = __half22float2(*(__half2*)&u1.x);
            float2 b1 = __half22float2(*(__half2*)&u1.y);
            float2 a2 = __half22float2(*(__half2*)&u2.x);
            float2 b2 = __half22float2(*(__half2*)&u2.y);
            float2 a3 = __half22float2(*(__half2*)&u3.x);
            float2 b3 = __half22float2(*(__half2*)&u3.y);
            acc.x = fmaf(v0, a0.x, acc.x); acc.y = fmaf(v0, a0.y, acc.y);
            acc.z = fmaf(v0, b0.x, acc.z); acc.w = fmaf(v0, b0.y, acc.w);
            acc.x = fmaf(v1, a1.x, acc.x); acc.y = fmaf(v1, a1.y, acc.y);
            acc.z = fmaf(v1, b1.x, acc.z); acc.w = fmaf(v1, b1.y, acc.w);
            acc.x = fmaf(v2, a2.x, acc.x); acc.y = fmaf(v2, a2.y, acc.y);
            acc.z = fmaf(v2, b2.x, acc.z); acc.w = fmaf(v2, b2.y, acc.w);
            acc.x = fmaf(v3, a3.x, acc.x); acc.y = fmaf(v3, a3.y, acc.y);
            acc.z = fmaf(v3, b3.x, acc.z); acc.w = fmaf(v3, b3.y, acc.w);
        }
        for (; j < n; j++) {
            int   cj = __shfl_sync(0xffffffffu, c, j);
            float vj = __shfl_sync(0xffffffffu, v, j);
            uint2 u = *(const uint2*)(hb + (size_t)cj * NC);
            float2 a = __half22float2(*(__half2*)&u.x);
            float2 b = __half22float2(*(__half2*)&u.y);
            acc.x = fmaf(vj, a.x, acc.x); acc.y = fmaf(vj, a.y, acc.y);
            acc.z = fmaf(vj, b.x, acc.z); acc.w = fmaf(vj, b.y, acc.w);
        }
    }

    *(float4*)(g_agg + (size_t)row * NC + hop * NHID + lane * 4) = acc;
}

// ---------------------------------------------------------------------------
// GEMM2 (tensor): y = elu(agg) @ W_out + b_out.  elu + split fused in A stage.
// CTA tile 128x64, BK=32, 8 warps (4m x 2n), warp tile 32x32.
// ---------------------------------------------------------------------------
__device__ __forceinline__ float elu1(float v) {
    return v > 0.f ? v : (__expf(v) - 1.f);
}

__global__ __launch_bounds__(256) void gemm2_mma(const float* __restrict__ bout,
                                                 float* __restrict__ y) {
    const int m0 = blockIdx.x * 128;

    __shared__ __nv_bfloat16 Ash[128 * SA], Asl[128 * SA];
    __shared__ __nv_bfloat16 Bsh[64 * SA],  Bsl[64 * SA];

    const int t   = threadIdx.x;
    const int wid = t >> 5, lane = t & 31;
    const int wm  = wid >> 1, wn = wid & 1;
    const int g   = lane >> 2, t4 = lane & 3;

    const int ar = t >> 1;          // A row 0..127
    const int ac = (t & 1) * 16;    // A col block (16 f32)
    const int br = t >> 2;          // B row (n) 0..63
    const int bk = (t & 3) * 8;     // B col block (8 bf16)

    const int arow = m0 + ar;
    const bool aok = arow < NN;

    float acc[2][4][4];
#pragma unroll
    for (int i = 0; i < 2; i++)
#pragma unroll
        for (int j = 0; j < 4; j++)
#pragma unroll
            for (int q = 0; q < 4; q++) acc[i][j][q] = 0.f;

    const float4 zf = make_float4(0.f, 0.f, 0.f, 0.f);
    float4 fa[4];
    uint4 pb, pbl;

    {
        const float* ap = g_agg + (size_t)arow * NC + ac;
#pragma unroll
        for (int q = 0; q < 4; q++)
            fa[q] = aok ? *(const float4*)(ap + q * 4) : zf;
        pb  = *(const uint4*)(g_woth + (size_t)br * NC + bk);
        pbl = *(const uint4*)(g_wotl + (size_t)br * NC + bk);
    }

    for (int k0 = 0; k0 < NC; k0 += 32) {
        __syncthreads();
#pragma unroll
        for (int q = 0; q < 2; q++) {
            float v[8] = {fa[2*q].x, fa[2*q].y, fa[2*q].z, fa[2*q].w,
                          fa[2*q+1].x, fa[2*q+1].y, fa[2*q+1].z, fa[2*q+1].w};
            union { uint4 u; __nv_bfloat16 b[8]; } uh, ul;
#pragma unroll
            for (int j = 0; j < 8; j++) {
                float e = elu1(v[j]);
                split_bf16(e, uh.b[j], ul.b[j]);
            }
            *(uint4*)&Ash[ar * SA + ac + q * 8] = uh.u;
            *(uint4*)&Asl[ar * SA + ac + q * 8] = ul.u;
        }
        *(uint4*)&Bsh[br * SA + bk] = pb;
        *(uint4*)&Bsl[br * SA + bk] = pbl;
        __syncthreads();

        const int kn = k0 + 32;
        if (kn < NC) {
            const float* ap = g_agg + (size_t)arow * NC + kn + ac;
#pragma unroll
            for (int q = 0; q < 4; q++)
                fa[q] = aok ? *(const float4*)(ap + q * 4) : zf;
            pb  = *(const uint4*)(g_woth + (size_t)br * NC + kn + bk);
            pbl = *(const uint4*)(g_wotl + (size_t)br * NC + kn + bk);
        }

#pragma unroll
        for (int ks = 0; ks < 2; ks++) {
            const int kb = ks * 16 + 2 * t4;
            uint32_t ah[2][4], al[2][4];
#pragma unroll
            for (int mf = 0; mf < 2; mf++) {
                const int rb = (wm * 32 + mf * 16 + g) * SA + kb;
                ah[mf][0] = lds32(&Ash[rb]);
                ah[mf][1] = lds32(&Ash[rb + 8 * SA]);
                ah[mf][2] = lds32(&Ash[rb + 8]);
                ah[mf][3] = lds32(&Ash[rb + 8 * SA + 8]);
                al[mf][0] = lds32(&Asl[rb]);
                al[mf][1] = lds32(&Asl[rb + 8 * SA]);
                al[mf][2] = lds32(&Asl[rb + 8]);
                al[mf][3] = lds32(&Asl[rb + 8 * SA + 8]);
            }
#pragma unroll
            for (int nf = 0; nf < 4; nf++) {
                const int nb = (wn * 32 + nf * 8 + g) * SA + kb;
                uint32_t bh[2], bl[2];
                bh[0] = lds32(&Bsh[nb]); bh[1] = lds32(&Bsh[nb + 8]);
                bl[0] = lds32(&Bsl[nb]); bl[1] = lds32(&Bsl[nb + 8]);
#pragma unroll
                for (int mf = 0; mf < 2; mf++) {
                    mma16816(acc[mf][nf], ah[mf], bh);
                    mma16816(acc[mf][nf], ah[mf], bl);
                    mma16816(acc[mf][nf], al[mf], bh);
                }
            }
        }
    }

    const int colbase = wn * 32 + 2 * t4;
#pragma unroll
    for (int mf = 0; mf < 2; mf++) {
        const int row = m0 + wm * 32 + mf * 16 + g;
#pragma unroll
        for (int nf = 0; nf < 4; nf++) {
            const int col = colbase + nf * 8;
            const float2 bv = *(const float2*)(bout + col);
            if (row < NN) {
                float2 o;
                o.x = acc[mf][nf][0] + bv.x;
                o.y = acc[mf][nf][1] + bv.y;
                *(float2*)(y + (size_t)row * NO + col) = o;
            }
            if (row + 8 < NN) {
                float2 o;
                o.x = acc[mf][nf][2] + bv.x;
                o.y = acc[mf][nf][3] + bv.y;
                *(float2*)(y + (size_t)(row + 8) * NO + col) = o;
            }
        }
    }
}

// ---------------------------------------------------------------------------
// Launch. Inputs: x, W, b, W_out, b_out, edge_rows, edge_cols, edge_vals.
// ---------------------------------------------------------------------------
extern "C" void kernel_launch(void* const* d_in, const int* in_sizes, int n_in,
                              void* d_out, int out_size) {
    (void)in_sizes; (void)n_in; (void)out_size;
    const float* x     = (const float*)d_in[0];
    const float* W     = (const float*)d_in[1];
    const float* b     = (const float*)d_in[2];
    const float* Wout  = (const float*)d_in[3];
    const float* bout  = (const float*)d_in[4];
    const int*   erows = (const int*)d_in[5];
    const int*   ecols = (const int*)d_in[6];
    const float* evals = (const float*)d_in[7];
    float* y = (float*)d_out;

    // prep (zero counters + weight splits) and CSR build
    prep<<<(NBIN + 255) / 256, 256>>>(W, Wout);
    hist<<<NET / 256, 256>>>(erows);
    scan1<<<SCAN_NB, SCAN_BLK>>>();
    scan3<<<(NBIN + 255) / 256, 256>>>();
    scatter<<<NET / 256, 256>>>(erows, ecols, evals);

    // per-hop linear on tensor cores, fp16 h output
    gemm1_mma<<<dim3(KHOP, (NN + 127) / 128), 256>>>(x, b);

    // CSR SpMM, all hops in one launch (fp16 h fits L2 in full)
    spmm_csr<<<dim3((NN * 32 + 255) / 256, KHOP), 256>>>();

    // elu + output projection on tensor cores
    gemm2_mma<<<(NN + 127) / 128, 256>>>(bout, y);
}

// round 9
// speedup vs baseline: 2.4406x; 1.1729x over previous
#include <cuda_runtime.h>
#include <cuda_fp16.h>
#include <math.h>
#include <stdint.h>

#define NN   50000
#define NF   256
#define NHID 128
#define KHOP 4
#define NC   512      // KHOP * NHID
#define NE   800000
#define NO   64
#define SA   40       // smem row stride in fp16 elems (80B, conflict-free frags)

#define NBIN (KHOP * NN)        // 200000 row bins across all hops
#define NET  (KHOP * NE)        // 3200000 edges total
#define SCAN_BLK   256
#define SCAN_PER   16
#define SCAN_CHUNK (SCAN_BLK * SCAN_PER)   // 4096
#define SCAN_NB    49                       // ceil(NBIN / SCAN_CHUNK)

// ---------------------------------------------------------------------------
// Scratch (__device__ globals per harness allocation rules)
// ---------------------------------------------------------------------------
__device__ __half g_h[(size_t)NN * NC];    // post-linear features, fp16
__device__ float  g_agg[(size_t)NN * NC];  // SpMM output, fp32 (written once)
__device__ __half g_wt[KHOP * NHID * NF];  // W transposed [hop][n][k], fp16
__device__ __half g_wot[NO * NC];          // W_out transposed [n][k], fp16
// CSR build (recomputed every call; deterministic work)
__device__ int  g_cnt[NBIN];
__device__ int  g_rowptr[NBIN + 1];
__device__ int  g_cur[NBIN];
__device__ int  g_bsum[SCAN_NB];
__device__ int2 g_edge[NET];               // interleaved (col, val-bits)

// ---------------------------------------------------------------------------
// mma.sync m16n8k16 fp16 -> f32, helpers
// ---------------------------------------------------------------------------
__device__ __forceinline__ void mma16816(float* d, const uint32_t* a, const uint32_t* b) {
    asm volatile(
        "mma.sync.aligned.m16n8k16.row.col.f32.f16.f16.f32 "
        "{%0,%1,%2,%3}, {%4,%5,%6,%7}, {%8,%9}, {%0,%1,%2,%3};\n"
        : "+f"(d[0]), "+f"(d[1]), "+f"(d[2]), "+f"(d[3])
        : "r"(a[0]), "r"(a[1]), "r"(a[2]), "r"(a[3]), "r"(b[0]), "r"(b[1]));
}

__device__ __forceinline__ uint32_t lds32(const __half* p) {
    return *reinterpret_cast<const uint32_t*>(p);
}

__device__ __forceinline__ void split_h(float v, __half& h, __half& l) {
    h = __float2half_rn(v);
    l = __float2half_rn(v - __half2float(h));
}

// split 8 floats (2x float4) into hi/lo fp16 uint4 pair
__device__ __forceinline__ void split8(float4 a, float4 b, uint4& hh, uint4& ll) {
    union { uint4 u; __half s[8]; } H, L;
    float v[8] = {a.x, a.y, a.z, a.w, b.x, b.y, b.z, b.w};
#pragma unroll
    for (int j = 0; j < 8; j++) split_h(v[j], H.s[j], L.s[j]);
    hh = H.u; ll = L.u;
}

// ---------------------------------------------------------------------------
// Prep: zero CSR counters + both weight fp16 transposes, one kernel.
// ---------------------------------------------------------------------------
__global__ __launch_bounds__(256) void prep(const float* __restrict__ W,
                                            const float* __restrict__ Wout) {
    const int idx = blockIdx.x * 256 + threadIdx.x;
    if (idx < NBIN) g_cnt[idx] = 0;
    if (idx < KHOP * NF * NHID) {
        int hop = idx / (NF * NHID);
        int rem = idx - hop * (NF * NHID);
        int k = rem / NHID;
        int n = rem - k * NHID;
        g_wt[(size_t)hop * NHID * NF + (size_t)n * NF + k] = __float2half_rn(W[idx]);
    }
    if (idx < NC * NO) {
        int k = idx / NO;
        int n = idx - k * NO;
        g_wot[(size_t)n * NC + k] = __float2half_rn(Wout[idx]);
    }
}

// ---------------------------------------------------------------------------
// CSR build: histogram -> two-level scan -> scatter. Scan is global across
// hops (each hop sums to exactly NE, so hop h lands in [h*NE, (h+1)*NE)).
// ---------------------------------------------------------------------------
__global__ __launch_bounds__(256) void hist(const int* __restrict__ erows) {
    int e = blockIdx.x * 256 + threadIdx.x;
    if (e >= NET) return;
    int hop = e / NE;
    atomicAdd(&g_cnt[hop * NN + erows[e]], 1);
}

__global__ __launch_bounds__(SCAN_BLK) void scan1() {
    __shared__ int sh[SCAN_BLK];
    const int t = threadIdx.x;
    const int base = blockIdx.x * SCAN_CHUNK + t * SCAN_PER;
    int v[SCAN_PER];
    int tot = 0;
#pragma unroll
    for (int i = 0; i < SCAN_PER; i++) {
        v[i] = (base + i < NBIN) ? g_cnt[base + i] : 0;
        tot += v[i];
    }
    sh[t] = tot;
    __syncthreads();
    for (int off = 1; off < SCAN_BLK; off <<= 1) {
        int x = (t >= off) ? sh[t - off] : 0;
        __syncthreads();
        sh[t] += x;
        __syncthreads();
    }
    int run = sh[t] - tot;
#pragma unroll
    for (int i = 0; i < SCAN_PER; i++) {
        if (base + i < NBIN) g_rowptr[base + i] = run;
        run += v[i];
    }
    if (t == 0) g_bsum[blockIdx.x] = sh[SCAN_BLK - 1];
}

__global__ __launch_bounds__(256) void scan3() {
    int i = blockIdx.x * 256 + threadIdx.x;
    if (i < NBIN) {
        const int nb = i / SCAN_CHUNK;
        int pre = 0;
        for (int b = 0; b < nb; b++) pre += g_bsum[b];
        int v = g_rowptr[i] + pre;
        g_rowptr[i] = v;
        g_cur[i] = v;
    }
    if (i == 0) g_rowptr[NBIN] = NET;
}

__global__ __launch_bounds__(256) void scatter(const int* __restrict__ erows,
                                               const int* __restrict__ ecols,
                                               const float* __restrict__ evals) {
    int e = blockIdx.x * 256 + threadIdx.x;
    if (e >= NET) return;
    int hop = e / NE;
    int pos = atomicAdd(&g_cur[hop * NN + erows[e]], 1);
    g_edge[pos] = make_int2(ecols[e], __float_as_int(evals[e]));
}

// ---------------------------------------------------------------------------
// GEMM1 (tensor): g_h[n, hop*128+j] = fp16(x @ W[hop] + b[hop])
// 2-pass fp16-split: A = xh + xl (fp16 hi/lo, split in-kernel), B = W fp16.
// CTA tile 128x128, BK=32, 8 warps (4m x 2n), warp tile 32x64.
// ---------------------------------------------------------------------------
__global__ __launch_bounds__(256) void gemm1_mma(const float* __restrict__ x,
                                                 const float* __restrict__ bias) {
    const int hop = blockIdx.x;
    const int m0  = blockIdx.y * 128;

    __shared__ __half Ash[128 * SA], Asl[128 * SA];
    __shared__ __half Bs[128 * SA];

    const int t    = threadIdx.x;
    const int wid  = t >> 5, lane = t & 31;
    const int wm   = wid >> 1, wn = wid & 1;
    const int g    = lane >> 2, t4 = lane & 3;

    const int lr = t >> 2;          // 0..63
    const int lk = (t & 3) * 8;     // 0,8,16,24

    const __half* wt = g_wt + (size_t)hop * NHID * NF;

    float acc[2][8][4];
#pragma unroll
    for (int i = 0; i < 2; i++)
#pragma unroll
        for (int j = 0; j < 8; j++)
#pragma unroll
            for (int q = 0; q < 4; q++) acc[i][j][q] = 0.f;

    const float4 zf = make_float4(0.f, 0.f, 0.f, 0.f);
    float4 fx0a, fx0b, fx1a, fx1b;
    uint4 pb0, pb1;

    const int r0 = m0 + lr, r1 = m0 + lr + 64;
    {   // prefetch k0 = 0
        fx0a = (r0 < NN) ? *(const float4*)(x + (size_t)r0 * NF + lk)     : zf;
        fx0b = (r0 < NN) ? *(const float4*)(x + (size_t)r0 * NF + lk + 4) : zf;
        fx1a = (r1 < NN) ? *(const float4*)(x + (size_t)r1 * NF + lk)     : zf;
        fx1b = (r1 < NN) ? *(const float4*)(x + (size_t)r1 * NF + lk + 4) : zf;
        pb0  = *(const uint4*)(wt + (size_t)lr * NF + lk);
        pb1  = *(const uint4*)(wt + (size_t)(lr + 64) * NF + lk);
    }

    for (int k0 = 0; k0 < NF; k0 += 32) {
        __syncthreads();
        {
            uint4 hh, ll;
            split8(fx0a, fx0b, hh, ll);
            *(uint4*)&Ash[lr * SA + lk] = hh;
            *(uint4*)&Asl[lr * SA + lk] = ll;
            split8(fx1a, fx1b, hh, ll);
            *(uint4*)&Ash[(lr + 64) * SA + lk] = hh;
            *(uint4*)&Asl[(lr + 64) * SA + lk] = ll;
        }
        *(uint4*)&Bs[lr * SA + lk]        = pb0;
        *(uint4*)&Bs[(lr + 64) * SA + lk] = pb1;
        __syncthreads();

        const int kn = k0 + 32;
        if (kn < NF) {   // prefetch next K-block
            fx0a = (r0 < NN) ? *(const float4*)(x + (size_t)r0 * NF + kn + lk)     : zf;
            fx0b = (r0 < NN) ? *(const float4*)(x + (size_t)r0 * NF + kn + lk + 4) : zf;
            fx1a = (r1 < NN) ? *(const float4*)(x + (size_t)r1 * NF + kn + lk)     : zf;
            fx1b = (r1 < NN) ? *(const float4*)(x + (size_t)r1 * NF + kn + lk + 4) : zf;
            pb0  = *(const uint4*)(wt + (size_t)lr * NF + kn + lk);
            pb1  = *(const uint4*)(wt + (size_t)(lr + 64) * NF + kn + lk);
        }

#pragma unroll
        for (int ks = 0; ks < 2; ks++) {
            const int kb = ks * 16 + 2 * t4;
            uint32_t ah[2][4], al[2][4];
#pragma unroll
            for (int mf = 0; mf < 2; mf++) {
                const int rb = (wm * 32 + mf * 16 + g) * SA + kb;
                ah[mf][0] = lds32(&Ash[rb]);
                ah[mf][1] = lds32(&Ash[rb + 8 * SA]);
                ah[mf][2] = lds32(&Ash[rb + 8]);
                ah[mf][3] = lds32(&Ash[rb + 8 * SA + 8]);
                al[mf][0] = lds32(&Asl[rb]);
                al[mf][1] = lds32(&Asl[rb + 8 * SA]);
                al[mf][2] = lds32(&Asl[rb + 8]);
                al[mf][3] = lds32(&Asl[rb + 8 * SA + 8]);
            }
#pragma unroll
            for (int nf = 0; nf < 8; nf++) {
                const int nb = (wn * 64 + nf * 8 + g) * SA + kb;
                uint32_t bb[2];
                bb[0] = lds32(&Bs[nb]); bb[1] = lds32(&Bs[nb + 8]);
#pragma unroll
                for (int mf = 0; mf < 2; mf++) {
                    mma16816(acc[mf][nf], ah[mf], bb);
                    mma16816(acc[mf][nf], al[mf], bb);
                }
            }
        }
    }

    const int colbase = wn * 64 + 2 * t4;
#pragma unroll
    for (int mf = 0; mf < 2; mf++) {
        const int row = m0 + wm * 32 + mf * 16 + g;
#pragma unroll
        for (int nf = 0; nf < 8; nf++) {
            const int col = colbase + nf * 8;
            const float2 bv = *(const float2*)(bias + hop * NHID + col);
            if (row < NN) {
                *(__half2*)(g_h + (size_t)row * NC + hop * NHID + col) =
                    __floats2half2_rn(acc[mf][nf][0] + bv.x, acc[mf][nf][1] + bv.y);
            }
            if (row + 8 < NN) {
                *(__half2*)(g_h + (size_t)(row + 8) * NC + hop * NHID + col) =
                    __floats2half2_rn(acc[mf][nf][2] + bv.x, acc[mf][nf][3] + bv.y);
            }
        }
    }
}

// ---------------------------------------------------------------------------
// CSR SpMM, all hops in one launch (fp16 h: whole 51.2MB set is L2-resident).
// One warp per row, fp32 register accumulation, single fp32 write. Lane owns
// 4 features (8B fp16 gather per edge). Interleaved (col,val) edge records.
// ---------------------------------------------------------------------------
__global__ __launch_bounds__(256) void spmm_csr() {
    const int row  = (blockIdx.x * 256 + threadIdx.x) >> 5;
    const int lane = threadIdx.x & 31;
    if (row >= NN) return;
    const int hop = blockIdx.y;

    const int bin = hop * NN + row;
    const int s = g_rowptr[bin];
    const int e = g_rowptr[bin + 1];

    const __half* hb = g_h + hop * NHID + lane * 4;
    float4 acc = make_float4(0.f, 0.f, 0.f, 0.f);

    for (int p = s; p < e; p += 32) {
        const int n = min(32, e - p);
        int2 ed = (lane < n) ? g_edge[p + lane] : make_int2(0, 0);
        const int   c = ed.x;
        const float v = __int_as_float(ed.y);
        int j = 0;
        for (; j + 4 <= n; j += 4) {
            int   c0 = __shfl_sync(0xffffffffu, c, j);
            int   c1 = __shfl_sync(0xffffffffu, c, j + 1);
            int   c2 = __shfl_sync(0xffffffffu, c, j + 2);
            int   c3 = __shfl_sync(0xffffffffu, c, j + 3);
            float v0 = __shfl_sync(0xffffffffu, v, j);
            float v1 = __shfl_sync(0xffffffffu, v, j + 1);
            float v2 = __shfl_sync(0xffffffffu, v, j + 2);
            float v3 = __shfl_sync(0xffffffffu, v, j + 3);
            uint2 u0 = *(const uint2*)(hb + (size_t)c0 * NC);
            uint2 u1 = *(const uint2*)(hb + (size_t)c1 * NC);
            uint2 u2 = *(const uint2*)(hb + (size_t)c2 * NC);
            uint2 u3 = *(const uint2*)(hb + (size_t)c3 * NC);
            float2 a0 = __half22float2(*(__half2*)&u0.x);
            float2 b0 = __half22float2(*(__half2*)&u0.y);
            float2 a1 = __half22float2(*(__half2*)&u1.x);
            float2 b1 = __half22float2(*(__half2*)&u1.y);
            float2 a2 = __half22float2(*(__half2*)&u2.x);
            float2 b2 = __half22float2(*(__half2*)&u2.y);
            float2 a3 = __half22float2(*(__half2*)&u3.x);
            float2 b3 = __half22float2(*(__half2*)&u3.y);
            acc.x = fmaf(v0, a0.x, acc.x); acc.y = fmaf(v0, a0.y, acc.y);
            acc.z = fmaf(v0, b0.x, acc.z); acc.w = fmaf(v0, b0.y, acc.w);
            acc.x = fmaf(v1, a1.x, acc.x); acc.y = fmaf(v1, a1.y, acc.y);
            acc.z = fmaf(v1, b1.x, acc.z); acc.w = fmaf(v1, b1.y, acc.w);
            acc.x = fmaf(v2, a2.x, acc.x); acc.y = fmaf(v2, a2.y, acc.y);
            acc.z = fmaf(v2, b2.x, acc.z); acc.w = fmaf(v2, b2.y, acc.w);
            acc.x = fmaf(v3, a3.x, acc.x); acc.y = fmaf(v3, a3.y, acc.y);
            acc.z = fmaf(v3, b3.x, acc.z); acc.w = fmaf(v3, b3.y, acc.w);
        }
        for (; j < n; j++) {
            int   cj = __shfl_sync(0xffffffffu, c, j);
            float vj = __shfl_sync(0xffffffffu, v, j);
            uint2 u = *(const uint2*)(hb + (size_t)cj * NC);
            float2 a = __half22float2(*(__half2*)&u.x);
            float2 b = __half22float2(*(__half2*)&u.y);
            acc.x = fmaf(vj, a.x, acc.x); acc.y = fmaf(vj, a.y, acc.y);
            acc.z = fmaf(vj, b.x, acc.z); acc.w = fmaf(vj, b.y, acc.w);
        }
    }

    *(float4*)(g_agg + (size_t)row * NC + hop * NHID + lane * 4) = acc;
}

// ---------------------------------------------------------------------------
// GEMM2 (tensor): y = elu(agg) @ W_out + b_out.
// 2-pass fp16-split: A = elu(agg) hi/lo fp16 (fused), B = Wout fp16.
// CTA tile 128x64, BK=32, 8 warps (4m x 2n), warp tile 32x32.
// ---------------------------------------------------------------------------
__device__ __forceinline__ float elu1(float v) {
    return v > 0.f ? v : (__expf(v) - 1.f);
}

__global__ __launch_bounds__(256) void gemm2_mma(const float* __restrict__ bout,
                                                 float* __restrict__ y) {
    const int m0 = blockIdx.x * 128;

    __shared__ __half Ash[128 * SA], Asl[128 * SA];
    __shared__ __half Bs[64 * SA];

    const int t   = threadIdx.x;
    const int wid = t >> 5, lane = t & 31;
    const int wm  = wid >> 1, wn = wid & 1;
    const int g   = lane >> 2, t4 = lane & 3;

    const int ar = t >> 1;          // A row 0..127
    const int ac = (t & 1) * 16;    // A col block (16 f32)
    const int br = t >> 2;          // B row (n) 0..63
    const int bk = (t & 3) * 8;     // B col block (8 fp16)

    const int arow = m0 + ar;
    const bool aok = arow < NN;

    float acc[2][4][4];
#pragma unroll
    for (int i = 0; i < 2; i++)
#pragma unroll
        for (int j = 0; j < 4; j++)
#pragma unroll
            for (int q = 0; q < 4; q++) acc[i][j][q] = 0.f;

    const float4 zf = make_float4(0.f, 0.f, 0.f, 0.f);
    float4 fa[4];
    uint4 pb;

    {
        const float* ap = g_agg + (size_t)arow * NC + ac;
#pragma unroll
        for (int q = 0; q < 4; q++)
            fa[q] = aok ? *(const float4*)(ap + q * 4) : zf;
        pb = *(const uint4*)(g_wot + (size_t)br * NC + bk);
    }

    for (int k0 = 0; k0 < NC; k0 += 32) {
        __syncthreads();
#pragma unroll
        for (int q = 0; q < 2; q++) {
            float4 va = fa[2 * q], vb = fa[2 * q + 1];
            va.x = elu1(va.x); va.y = elu1(va.y); va.z = elu1(va.z); va.w = elu1(va.w);
            vb.x = elu1(vb.x); vb.y = elu1(vb.y); vb.z = elu1(vb.z); vb.w = elu1(vb.w);
            uint4 hh, ll;
            split8(va, vb, hh, ll);
            *(uint4*)&Ash[ar * SA + ac + q * 8] = hh;
            *(uint4*)&Asl[ar * SA + ac + q * 8] = ll;
        }
        *(uint4*)&Bs[br * SA + bk] = pb;
        __syncthreads();

        const int kn = k0 + 32;
        if (kn < NC) {
            const float* ap = g_agg + (size_t)arow * NC + kn + ac;
#pragma unroll
            for (int q = 0; q < 4; q++)
                fa[q] = aok ? *(const float4*)(ap + q * 4) : zf;
            pb = *(const uint4*)(g_wot + (size_t)br * NC + kn + bk);
        }

#pragma unroll
        for (int ks = 0; ks < 2; ks++) {
            const int kb = ks * 16 + 2 * t4;
            uint32_t ah[2][4], al[2][4];
#pragma unroll
            for (int mf = 0; mf < 2; mf++) {
                const int rb = (wm * 32 + mf * 16 + g) * SA + kb;
                ah[mf][0] = lds32(&Ash[rb]);
                ah[mf][1] = lds32(&Ash[rb + 8 * SA]);
                ah[mf][2] = lds32(&Ash[rb + 8]);
                ah[mf][3] = lds32(&Ash[rb + 8 * SA + 8]);
                al[mf][0] = lds32(&Asl[rb]);
                al[mf][1] = lds32(&Asl[rb + 8 * SA]);
                al[mf][2] = lds32(&Asl[rb + 8]);
                al[mf][3] = lds32(&Asl[rb + 8 * SA + 8]);
            }
#pragma unroll
            for (int nf = 0; nf < 4; nf++) {
                const int nb = (wn * 32 + nf * 8 + g) * SA + kb;
                uint32_t bb[2];
                bb[0] = lds32(&Bs[nb]); bb[1] = lds32(&Bs[nb + 8]);
#pragma unroll
                for (int mf = 0; mf < 2; mf++) {
                    mma16816(acc[mf][nf], ah[mf], bb);
                    mma16816(acc[mf][nf], al[mf], bb);
                }
            }
        }
    }

    const int colbase = wn * 32 + 2 * t4;
#pragma unroll
    for (int mf = 0; mf < 2; mf++) {
        const int row = m0 + wm * 32 + mf * 16 + g;
#pragma unroll
        for (int nf = 0; nf < 4; nf++) {
            const int col = colbase + nf * 8;
            const float2 bv = *(const float2*)(bout + col);
            if (row < NN) {
                float2 o;
                o.x = acc[mf][nf][0] + bv.x;
                o.y = acc[mf][nf][1] + bv.y;
                *(float2*)(y + (size_t)row * NO + col) = o;
            }
            if (row + 8 < NN) {
                float2 o;
                o.x = acc[mf][nf][2] + bv.x;
                o.y = acc[mf][nf][3] + bv.y;
                *(float2*)(y + (size_t)(row + 8) * NO + col) = o;
            }
        }
    }
}

// ---------------------------------------------------------------------------
// Launch. Inputs: x, W, b, W_out, b_out, edge_rows, edge_cols, edge_vals.
// ---------------------------------------------------------------------------
extern "C" void kernel_launch(void* const* d_in, const int* in_sizes, int n_in,
                              void* d_out, int out_size) {
    (void)in_sizes; (void)n_in; (void)out_size;
    const float* x     = (const float*)d_in[0];
    const float* W     = (const float*)d_in[1];
    const float* b     = (const float*)d_in[2];
    const float* Wout  = (const float*)d_in[3];
    const float* bout  = (const float*)d_in[4];
    const int*   erows = (const int*)d_in[5];
    const int*   ecols = (const int*)d_in[6];
    const float* evals = (const float*)d_in[7];
    float* y = (float*)d_out;

    // prep (zero counters + weight fp16 transposes) and CSR build
    prep<<<(NBIN + 255) / 256, 256>>>(W, Wout);
    hist<<<NET / 256, 256>>>(erows);
    scan1<<<SCAN_NB, SCAN_BLK>>>();
    scan3<<<(NBIN + 255) / 256, 256>>>();
    scatter<<<NET / 256, 256>>>(erows, ecols, evals);

    // per-hop linear on tensor cores (2-pass fp16-split), fp16 h output
    gemm1_mma<<<dim3(KHOP, (NN + 127) / 128), 256>>>(x, b);

    // CSR SpMM, all hops in one launch (fp16 h fits L2 in full)
    spmm_csr<<<dim3((NN * 32 + 255) / 256, KHOP), 256>>>();

    // elu + output projection on tensor cores (2-pass fp16-split)
    gemm2_mma<<<(NN + 127) / 128, 256>>>(bout, y);
}